// round 1
// baseline (speedup 1.0000x reference)
#include <cuda_runtime.h>
#include <cstdint>
#include <cstddef>

// Problem constants (fixed shapes)
#define T_DIM 64
#define B_DIM 512
#define C_DIM 512
#define H_DIM 512
#define E_DIM 128
#define NC_DIM 96
#define S_DIM 32

// ---------------- scratch (device globals; no allocations allowed) ----------
__device__ float g_fproj[(size_t)T_DIM * B_DIM * H_DIM];      // 67 MB
__device__ float g_hpgh[B_DIM * 2048];                        // [B, 512 hp | 1536 gh]
__device__ float g_x[B_DIM * (C_DIM + E_DIM)];                // [B, 640]
__device__ float g_gi[B_DIM * 3 * H_DIM];                     // [B, 1536]
__device__ float g_hidden[B_DIM * H_DIM];                     // [B, 512]
__device__ float g_hs[(size_t)S_DIM * B_DIM * H_DIM];         // stored as (b*S+s) rows
__device__ int   g_text[B_DIM * S_DIM];

// ---------------- text dtype normalization (int64-or-int32 -> int32) --------
__global__ void textnorm_kernel(const int* __restrict__ raw) {
    __shared__ int is32;
    int tid = threadIdx.x;
    if (tid == 0) is32 = 0;
    __syncthreads();
    int local = 0;
    // If data is int64 (values < 96), every odd 32-bit word is 0.
    // If data is int32, odd words are random labels (nonzero w.h.p.).
    // Reads stay within min footprint (16384 * 4 bytes).
    for (int i = tid; i < 8192; i += blockDim.x) local |= raw[2 * i + 1];
    if (local) atomicOr(&is32, 1);
    __syncthreads();
    if (is32) {
        for (int i = tid; i < B_DIM * S_DIM; i += blockDim.x) g_text[i] = raw[i];
    } else {
        for (int i = tid; i < B_DIM * S_DIM; i += blockDim.x) g_text[i] = raw[2 * i];
    }
}

// ---------------- generic fp32 GEMM: C[M,N] = A[M,K] @ W[N,K]^T + bias ------
// Dual-weight: rows n < nsplit come from W1/b1, rows >= nsplit from W2/b2.
// aZero: treat A as all-zeros (writes bias only) -- used at step 0.
template<int BM, int BN, int TM, int TN>
__global__ void gemm_nt(const float* __restrict__ A,
                        const float* __restrict__ W1, const float* __restrict__ W2,
                        int nsplit,
                        const float* __restrict__ b1, const float* __restrict__ b2,
                        float* __restrict__ C,
                        int M, int N, int K, int aZero)
{
    constexpr int BK = 8;
    constexpr int TX = BN / TN;
    constexpr int TY = BM / TM;
    static_assert(TX * TY == 256, "blockDim must be 256");

    const int tid = threadIdx.x;
    const int tx = tid % TX, ty = tid / TX;
    const int n0 = blockIdx.x * BN, m0 = blockIdx.y * BM;

    if (aZero) {
        #pragma unroll
        for (int i = 0; i < TM; i++) {
            int m = m0 + ty * TM + i;
            if (m >= M) continue;
            #pragma unroll
            for (int j = 0; j < TN; j++) {
                int n = n0 + tx * TN + j;
                if (n < N) {
                    float bv = 0.f;
                    if (b1) bv = (n < nsplit) ? b1[n] : b2[n - nsplit];
                    C[(size_t)m * N + n] = bv;
                }
            }
        }
        return;
    }

    __shared__ float As[BK][BM];
    __shared__ float Bs[BK][BN];

    float acc[TM][TN];
    #pragma unroll
    for (int i = 0; i < TM; i++)
        #pragma unroll
        for (int j = 0; j < TN; j++) acc[i][j] = 0.f;

    for (int k0 = 0; k0 < K; k0 += BK) {
        // load A tile [BM x 8] (K-contiguous), store transposed
        for (int i = tid; i < BM * 2; i += 256) {
            int r = i >> 1, kq = (i & 1) * 4;
            float4 v = make_float4(0.f, 0.f, 0.f, 0.f);
            int m = m0 + r;
            if (m < M) v = *(const float4*)(A + (size_t)m * K + k0 + kq);
            As[kq + 0][r] = v.x; As[kq + 1][r] = v.y;
            As[kq + 2][r] = v.z; As[kq + 3][r] = v.w;
        }
        // load W tile [BN x 8]
        for (int i = tid; i < BN * 2; i += 256) {
            int r = i >> 1, kq = (i & 1) * 4;
            int n = n0 + r;
            float4 v = make_float4(0.f, 0.f, 0.f, 0.f);
            if (n < N) {
                const float* Wp = (n < nsplit) ? (W1 + (size_t)n * K)
                                               : (W2 + (size_t)(n - nsplit) * K);
                v = *(const float4*)(Wp + k0 + kq);
            }
            Bs[kq + 0][r] = v.x; Bs[kq + 1][r] = v.y;
            Bs[kq + 2][r] = v.z; Bs[kq + 3][r] = v.w;
        }
        __syncthreads();

        #pragma unroll
        for (int k = 0; k < BK; k++) {
            float a[TM], bb[TN];
            #pragma unroll
            for (int i = 0; i < TM; i += 4)
                *(float4*)&a[i] = *(const float4*)&As[k][ty * TM + i];
            #pragma unroll
            for (int j = 0; j < TN; j += 4)
                *(float4*)&bb[j] = *(const float4*)&Bs[k][tx * TN + j];
            #pragma unroll
            for (int i = 0; i < TM; i++)
                #pragma unroll
                for (int j = 0; j < TN; j++)
                    acc[i][j] = fmaf(a[i], bb[j], acc[i][j]);
        }
        __syncthreads();
    }

    #pragma unroll
    for (int i = 0; i < TM; i++) {
        int m = m0 + ty * TM + i;
        if (m >= M) continue;
        #pragma unroll
        for (int j = 0; j < TN; j++) {
            int n = n0 + tx * TN + j;
            if (n < N) {
                float bv = 0.f;
                if (b1) bv = (n < nsplit) ? b1[n] : b2[n - nsplit];
                C[(size_t)m * N + n] = acc[i][j] + bv;
            }
        }
    }
}

// ---------------- fused attention: e -> softmax -> context -> x assemble ----
// One CTA per batch element b. Reads hp from g_hpgh[:, 0:512].
__global__ void att_kernel(const float* __restrict__ feature,
                           const float* __restrict__ Wscore,
                           const float* __restrict__ char_emb,
                           int s)
{
    __shared__ float hpS[H_DIM];
    __shared__ float wS[H_DIM];
    __shared__ float eS[T_DIM];

    const int b = blockIdx.x;
    const int tid = threadIdx.x;
    const int warp = tid >> 5, lane = tid & 31;

    for (int h = tid; h < H_DIM; h += 256) {
        hpS[h] = g_hpgh[b * 2048 + h];
        wS[h] = Wscore[h];
    }
    __syncthreads();

    // e[t] = sum_h tanh(fproj[t,b,h] + hp[h]) * w[h]  (one warp per t)
    for (int t = warp; t < T_DIM; t += 8) {
        const float* fp = g_fproj + ((size_t)t * B_DIM + b) * H_DIM;
        float p = 0.f;
        #pragma unroll 4
        for (int h = lane; h < H_DIM; h += 32)
            p += tanhf(fp[h] + hpS[h]) * wS[h];
        #pragma unroll
        for (int off = 16; off; off >>= 1) p += __shfl_xor_sync(0xFFFFFFFFu, p, off);
        if (lane == 0) eS[t] = p;
    }
    __syncthreads();

    // softmax over T=64 (warp 0)
    if (tid < 32) {
        float e1 = eS[tid], e2 = eS[tid + 32];
        float m = fmaxf(e1, e2);
        #pragma unroll
        for (int off = 16; off; off >>= 1) m = fmaxf(m, __shfl_xor_sync(0xFFFFFFFFu, m, off));
        float x1 = expf(e1 - m), x2 = expf(e2 - m);
        float ssum = x1 + x2;
        #pragma unroll
        for (int off = 16; off; off >>= 1) ssum += __shfl_xor_sync(0xFFFFFFFFu, ssum, off);
        float inv = 1.f / ssum;
        eS[tid] = x1 * inv;
        eS[tid + 32] = x2 * inv;
    }
    __syncthreads();

    // context[c] = sum_t alpha[t] * feature[t,b,c] ; write into x[b, 0:512]
    for (int c = tid; c < C_DIM; c += 256) {
        const float* f = feature + (size_t)b * C_DIM + c;
        float acc = 0.f;
        #pragma unroll 8
        for (int t = 0; t < T_DIM; t++)
            acc = fmaf(eS[t], f[(size_t)t * B_DIM * C_DIM], acc);
        g_x[b * (C_DIM + E_DIM) + c] = acc;
    }

    // emb: targets[s][b] = (s==0) ? 0 : text[b*S + s-1]
    int tgt = (s == 0) ? 0 : g_text[b * S_DIM + (s - 1)];
    for (int j = tid; j < E_DIM; j += 256)
        g_x[b * (C_DIM + E_DIM) + C_DIM + j] = char_emb[tgt * E_DIM + j];
}

// ---------------- GRU cell elementwise --------------------------------------
__global__ void gru_kernel(int s)
{
    int i = blockIdx.x * blockDim.x + threadIdx.x;   // over B*H = 262144
    int b = i >> 9, n = i & 511;

    const float* gib = g_gi + b * 1536;
    const float* ghb = g_hpgh + b * 2048 + 512;

    float ir = gib[n], iz = gib[512 + n], in = gib[1024 + n];
    float hr = ghb[n], hz = ghb[512 + n], hn = ghb[1024 + n];
    float h = (s == 0) ? 0.f : g_hidden[i];

    float r = 1.f / (1.f + expf(-(ir + hr)));
    float z = 1.f / (1.f + expf(-(iz + hz)));
    float nn = tanhf(in + r * hn);
    float hN = (1.f - z) * nn + z * h;

    g_hidden[i] = hN;
    g_hs[((size_t)b * S_DIM + s) * H_DIM + n] = hN;   // layout for final GEMM
}

// ---------------- host launch ------------------------------------------------
struct ScratchPtrs {
    float *fproj, *x, *gi, *hidden, *hs;
};

extern "C" void kernel_launch(void* const* d_in, const int* in_sizes, int n_in,
                              void* d_out, int out_size)
{
    (void)in_sizes; (void)n_in; (void)out_size;
    const float* feature  = (const float*)d_in[0];
    const int*   text_raw = (const int*)  d_in[1];
    const float* W_h2h    = (const float*)d_in[2];
    const float* b_h2h    = (const float*)d_in[3];
    const float* W_c2h    = (const float*)d_in[4];
    const float* W_score  = (const float*)d_in[5];
    const float* W_ih     = (const float*)d_in[6];
    const float* W_hh     = (const float*)d_in[7];
    const float* b_ih     = (const float*)d_in[8];
    const float* b_hh     = (const float*)d_in[9];
    const float* char_emb = (const float*)d_in[10];
    const float* W_gen    = (const float*)d_in[11];
    const float* b_gen    = (const float*)d_in[12];
    float* out = (float*)d_out;

    // Resolve device-global addresses once (no CUDA API calls during capture).
    static ScratchPtrs P = [] {
        ScratchPtrs p;
        cudaGetSymbolAddress((void**)&p.fproj,  g_fproj);
        cudaGetSymbolAddress((void**)&p.x,      g_x);
        cudaGetSymbolAddress((void**)&p.gi,     g_gi);
        cudaGetSymbolAddress((void**)&p.hidden, g_hidden);
        cudaGetSymbolAddress((void**)&p.hs,     g_hs);
        return p;
    }();
    float* hpgh;
    static float* hpgh_s = [] {
        float* q; cudaGetSymbolAddress((void**)&q, g_hpgh); return q;
    }();
    hpgh = hpgh_s;

    textnorm_kernel<<<1, 256>>>(text_raw);

    // fproj = feature(view [T*B, C]) @ W_c2h^T   (M=32768, N=512, K=512)
    gemm_nt<128, 128, 8, 8><<<dim3(4, 256), 256>>>(
        feature, W_c2h, W_c2h, 512, nullptr, nullptr,
        P.fproj, T_DIM * B_DIM, H_DIM, C_DIM, 0);

    for (int s = 0; s < S_DIM; s++) {
        // [hp | gh] = hidden @ [W_h2h ; W_hh]^T + [b_h2h ; b_hh]  (M=512, N=2048, K=512)
        gemm_nt<64, 64, 4, 4><<<dim3(32, 8), 256>>>(
            P.hidden, W_h2h, W_hh, 512, b_h2h, b_hh,
            hpgh, B_DIM, 2048, H_DIM, (s == 0) ? 1 : 0);

        att_kernel<<<B_DIM, 256>>>(feature, W_score, char_emb, s);

        // gi = x @ W_ih^T + b_ih   (M=512, N=1536, K=640)
        gemm_nt<64, 64, 4, 4><<<dim3(24, 8), 256>>>(
            P.x, W_ih, W_ih, 3 * H_DIM, b_ih, b_ih,
            P.gi, B_DIM, 3 * H_DIM, C_DIM + E_DIM, 0);

        gru_kernel<<<(B_DIM * H_DIM) / 256, 256>>>(s);
    }

    // probs = hs[(b*S+s), :] @ W_gen^T + b_gen   (M=16384, N=96, K=512)
    gemm_nt<128, 64, 8, 4><<<dim3(2, 128), 256>>>(
        P.hs, W_gen, W_gen, NC_DIM, b_gen, b_gen,
        out, B_DIM * S_DIM, NC_DIM, H_DIM, 0);
}

// round 2
// speedup vs baseline: 1.5242x; 1.5242x over previous
#include <cuda_runtime.h>
#include <cuda_fp16.h>
#include <cstdint>
#include <cstddef>

#define T_DIM 64
#define B_DIM 512
#define C_DIM 512
#define H_DIM 512
#define E_DIM 128
#define NC_DIM 96
#define S_DIM 32

// ---------------- scratch (device globals) ----------------------------------
__device__ __half2 g_fproj_h2[(size_t)T_DIM * B_DIM * (H_DIM / 2)]; // fp16 fproj
__device__ __half2 g_feat_h2[(size_t)T_DIM * B_DIM * (C_DIM / 2)]; // fp16 feature
__device__ float g_hpgh[B_DIM * 2048];
__device__ float g_x[B_DIM * (C_DIM + E_DIM)];
__device__ float g_gi[B_DIM * 3 * H_DIM];
__device__ float g_hidden[B_DIM * H_DIM];
__device__ float g_hs[(size_t)S_DIM * B_DIM * H_DIM];
__device__ int   g_text[B_DIM * S_DIM];
// pre-split weights (tf32 hi/lo)
__device__ float g_Whpgh_hi[2048 * 512], g_Whpgh_lo[2048 * 512];
__device__ float g_Wih_hi[1536 * 640],   g_Wih_lo[1536 * 640];
__device__ float g_Wc2h_hi[512 * 512],   g_Wc2h_lo[512 * 512];
__device__ float g_Wgen_hi[128 * 512],   g_Wgen_lo[128 * 512];   // padded 96->128
__device__ float g_bias_hpgh[2048];

// ---------------- helpers ----------------------------------------------------
__device__ __forceinline__ void split_tf32(float v, float& hi, float& lo) {
    uint32_t hb;
    asm("cvt.rna.tf32.f32 %0, %1;" : "=r"(hb) : "f"(v));
    float h = __uint_as_float(hb);
    float l = v - h;
    uint32_t lb;
    asm("cvt.rna.tf32.f32 %0, %1;" : "=r"(lb) : "f"(l));
    hi = h;
    lo = __uint_as_float(lb);
}

__device__ __forceinline__ void mma_tf32(float* d, const uint32_t* a, const uint32_t* b) {
    asm volatile(
        "mma.sync.aligned.m16n8k8.row.col.f32.tf32.tf32.f32 "
        "{%0,%1,%2,%3}, {%4,%5,%6,%7}, {%8,%9}, {%0,%1,%2,%3};\n"
        : "+f"(d[0]), "+f"(d[1]), "+f"(d[2]), "+f"(d[3])
        : "r"(a[0]), "r"(a[1]), "r"(a[2]), "r"(a[3]), "r"(b[0]), "r"(b[1]));
}

// ---------------- text dtype normalization ----------------------------------
__global__ void textnorm_kernel(const int* __restrict__ raw) {
    __shared__ int is32;
    int tid = threadIdx.x;
    if (tid == 0) is32 = 0;
    __syncthreads();
    int local = 0;
    for (int i = tid; i < 8192; i += blockDim.x) local |= raw[2 * i + 1];
    if (local) atomicOr(&is32, 1);
    __syncthreads();
    if (is32) {
        for (int i = tid; i < B_DIM * S_DIM; i += blockDim.x) g_text[i] = raw[i];
    } else {
        for (int i = tid; i < B_DIM * S_DIM; i += blockDim.x) g_text[i] = raw[2 * i];
    }
}

// ---------------- one-time transforms ----------------------------------------
__global__ void presplit_k(const float* __restrict__ src, float* __restrict__ hi,
                           float* __restrict__ lo, int n) {
    int i = blockIdx.x * blockDim.x + threadIdx.x;
    if (i < n) split_tf32(src[i], hi[i], lo[i]);
}

__global__ void presplit_pad_k(const float* __restrict__ src, float* __restrict__ hi,
                               float* __restrict__ lo, int nsrc, int ntot) {
    int i = blockIdx.x * blockDim.x + threadIdx.x;
    if (i >= ntot) return;
    if (i < nsrc) split_tf32(src[i], hi[i], lo[i]);
    else { hi[i] = 0.f; lo[i] = 0.f; }
}

__global__ void tohalf_k(const float* __restrict__ src, __half2* __restrict__ dst, int n2) {
    int i = blockIdx.x * blockDim.x + threadIdx.x;   // over half2 count
    if (i < n2) {
        float2 v = ((const float2*)src)[i];
        dst[i] = __floats2half2_rn(v.x, v.y);
    }
}

// ---------------- tf32 3-split tensor-core GEMM ------------------------------
// C[M,N] = A[M,K] @ W[N,K]^T + bias ; W pre-split into hi/lo arrays.
// 256 threads. BM x BN tile, BK=16. Warp tile WM x WN.
template<int BM, int BN, int WM, int WN, int OUT_HALF>
__global__ void __launch_bounds__(256, 1)
gemm_tf32(const float* __restrict__ A,
          const float* __restrict__ Whi, const float* __restrict__ Wlo,
          const float* __restrict__ bias,
          void* __restrict__ Cout, int M, int N, int K)
{
    constexpr int WARPS_M = BM / WM;
    constexpr int WARPS_N = BN / WN;
    static_assert(WARPS_M * WARPS_N == 8, "8 warps");
    constexpr int MT = WM / 16;
    constexpr int NT = WN / 8;
    constexpr int A_F4 = BM / 64;  // float4 loads per thread per stage
    constexpr int B_F4 = BN / 64;
    constexpr int LDA = 20;        // 16 + 4 pad (conflict-free fragment reads)

    extern __shared__ float smem[];
    float* Ahi = smem;                    // [2][BM*LDA]
    float* Alo = Ahi + 2 * BM * LDA;
    float* Bhi = Alo + 2 * BM * LDA;      // [2][BN*LDA]
    float* Blo = Bhi + 2 * BN * LDA;

    const int tid = threadIdx.x;
    const int warp = tid >> 5, lane = tid & 31;
    const int g = lane >> 2, c = lane & 3;
    const int wm = warp % WARPS_M, wn = warp / WARPS_M;
    const int n0 = blockIdx.x * BN, m0 = blockIdx.y * BM;

    float acc[MT][NT][4];
    #pragma unroll
    for (int i = 0; i < MT; i++)
        #pragma unroll
        for (int j = 0; j < NT; j++)
            #pragma unroll
            for (int q = 0; q < 4; q++) acc[i][j][q] = 0.f;

    const int KT = K / 16;

    // --- stage loaders ---
    auto loadStage = [&](int kt, float4* pa, float4* pbh, float4* pbl) {
        #pragma unroll
        for (int i = 0; i < A_F4; i++) {
            int idx = i * 256 + tid;
            int r = idx >> 2, kq = (idx & 3) << 2;
            pa[i] = *(const float4*)(A + (size_t)(m0 + r) * K + kt * 16 + kq);
        }
        #pragma unroll
        for (int i = 0; i < B_F4; i++) {
            int idx = i * 256 + tid;
            int r = idx >> 2, kq = (idx & 3) << 2;
            pbh[i] = *(const float4*)(Whi + (size_t)(n0 + r) * K + kt * 16 + kq);
            pbl[i] = *(const float4*)(Wlo + (size_t)(n0 + r) * K + kt * 16 + kq);
        }
    };
    auto storeStage = [&](int buf, const float4* pa, const float4* pbh, const float4* pbl) {
        #pragma unroll
        for (int i = 0; i < A_F4; i++) {
            int idx = i * 256 + tid;
            int r = idx >> 2, kq = (idx & 3) << 2;
            float* ah = Ahi + buf * BM * LDA + r * LDA + kq;
            float* al = Alo + buf * BM * LDA + r * LDA + kq;
            const float* v = (const float*)&pa[i];
            #pragma unroll
            for (int j = 0; j < 4; j++) split_tf32(v[j], ah[j], al[j]);
        }
        #pragma unroll
        for (int i = 0; i < B_F4; i++) {
            int idx = i * 256 + tid;
            int r = idx >> 2, kq = (idx & 3) << 2;
            float* bh = Bhi + buf * BN * LDA + r * LDA + kq;
            float* bl = Blo + buf * BN * LDA + r * LDA + kq;
            const float* vh = (const float*)&pbh[i];
            const float* vl = (const float*)&pbl[i];
            #pragma unroll
            for (int j = 0; j < 4; j++) { bh[j] = vh[j]; bl[j] = vl[j]; }
        }
    };

    {
        float4 pa[A_F4], pbh[B_F4], pbl[B_F4];
        loadStage(0, pa, pbh, pbl);
        storeStage(0, pa, pbh, pbl);
    }
    __syncthreads();

    int buf = 0;
    for (int kt = 0; kt < KT; kt++) {
        float4 pa[A_F4], pbh[B_F4], pbl[B_F4];
        const bool more = (kt + 1 < KT);
        if (more) loadStage(kt + 1, pa, pbh, pbl);

        const float* Ah = Ahi + buf * BM * LDA;
        const float* Al = Alo + buf * BM * LDA;
        const float* Bh = Bhi + buf * BN * LDA;
        const float* Bl = Blo + buf * BN * LDA;

        #pragma unroll
        for (int k8 = 0; k8 < 16; k8 += 8) {
            uint32_t aH[MT][4], aL[MT][4];
            #pragma unroll
            for (int mt = 0; mt < MT; mt++) {
                int mr = wm * WM + mt * 16 + g;
                aH[mt][0] = __float_as_uint(Ah[(mr)     * LDA + k8 + c]);
                aH[mt][1] = __float_as_uint(Ah[(mr + 8) * LDA + k8 + c]);
                aH[mt][2] = __float_as_uint(Ah[(mr)     * LDA + k8 + c + 4]);
                aH[mt][3] = __float_as_uint(Ah[(mr + 8) * LDA + k8 + c + 4]);
                aL[mt][0] = __float_as_uint(Al[(mr)     * LDA + k8 + c]);
                aL[mt][1] = __float_as_uint(Al[(mr + 8) * LDA + k8 + c]);
                aL[mt][2] = __float_as_uint(Al[(mr)     * LDA + k8 + c + 4]);
                aL[mt][3] = __float_as_uint(Al[(mr + 8) * LDA + k8 + c + 4]);
            }
            #pragma unroll
            for (int nt = 0; nt < NT; nt++) {
                int nc = wn * WN + nt * 8 + g;
                uint32_t bH[2], bL[2];
                bH[0] = __float_as_uint(Bh[nc * LDA + k8 + c]);
                bH[1] = __float_as_uint(Bh[nc * LDA + k8 + c + 4]);
                bL[0] = __float_as_uint(Bl[nc * LDA + k8 + c]);
                bL[1] = __float_as_uint(Bl[nc * LDA + k8 + c + 4]);
                #pragma unroll
                for (int mt = 0; mt < MT; mt++) {
                    mma_tf32(acc[mt][nt], aH[mt], bH);
                    mma_tf32(acc[mt][nt], aL[mt], bH);
                    mma_tf32(acc[mt][nt], aH[mt], bL);
                }
            }
        }

        if (more) storeStage(buf ^ 1, pa, pbh, pbl);
        __syncthreads();
        buf ^= 1;
    }

    // --- epilogue ---
    #pragma unroll
    for (int mt = 0; mt < MT; mt++) {
        #pragma unroll
        for (int nt = 0; nt < NT; nt++) {
            int m = m0 + wm * WM + mt * 16 + g;
            int n = n0 + wn * WN + nt * 8 + 2 * c;
            if (n >= N) continue;
            float bv0 = bias ? bias[n] : 0.f;
            float bv1 = bias ? bias[n + 1] : 0.f;
            float v0 = acc[mt][nt][0] + bv0, v1 = acc[mt][nt][1] + bv1;
            float v2 = acc[mt][nt][2] + bv0, v3 = acc[mt][nt][3] + bv1;
            if (OUT_HALF) {
                __half2* Ch = (__half2*)Cout;
                Ch[((size_t)m * N + n) >> 1] = __floats2half2_rn(v0, v1);
                Ch[((size_t)(m + 8) * N + n) >> 1] = __floats2half2_rn(v2, v3);
            } else {
                float* Cf = (float*)Cout;
                *(float2*)(Cf + (size_t)m * N + n) = make_float2(v0, v1);
                *(float2*)(Cf + (size_t)(m + 8) * N + n) = make_float2(v2, v3);
            }
        }
    }
}

// ---------------- fused attention --------------------------------------------
__global__ void att_kernel(const float* __restrict__ Wscore,
                           const float* __restrict__ char_emb, int s)
{
    __shared__ float hpS[H_DIM];
    __shared__ float wS[H_DIM];
    __shared__ float eS[T_DIM];

    const int b = blockIdx.x;
    const int tid = threadIdx.x;
    const int warp = tid >> 5, lane = tid & 31;

    for (int h = tid; h < H_DIM; h += 256) {
        hpS[h] = g_hpgh[b * 2048 + h];
        wS[h] = Wscore[h];
    }
    __syncthreads();

    // e[t] = sum_h tanh(fproj[t,b,h] + hp[h]) * w[h]
    for (int t = warp; t < T_DIM; t += 8) {
        const __half2* fp = g_fproj_h2 + ((size_t)t * B_DIM + b) * (H_DIM / 2);
        float p = 0.f;
        #pragma unroll 4
        for (int i = lane; i < H_DIM / 2; i += 32) {
            float2 f = __half22float2(fp[i]);
            p += tanhf(f.x + hpS[2 * i]) * wS[2 * i];
            p += tanhf(f.y + hpS[2 * i + 1]) * wS[2 * i + 1];
        }
        #pragma unroll
        for (int off = 16; off; off >>= 1) p += __shfl_xor_sync(0xFFFFFFFFu, p, off);
        if (lane == 0) eS[t] = p;
    }
    __syncthreads();

    if (tid < 32) {
        float e1 = eS[tid], e2 = eS[tid + 32];
        float m = fmaxf(e1, e2);
        #pragma unroll
        for (int off = 16; off; off >>= 1) m = fmaxf(m, __shfl_xor_sync(0xFFFFFFFFu, m, off));
        float x1 = expf(e1 - m), x2 = expf(e2 - m);
        float ssum = x1 + x2;
        #pragma unroll
        for (int off = 16; off; off >>= 1) ssum += __shfl_xor_sync(0xFFFFFFFFu, ssum, off);
        float inv = 1.f / ssum;
        eS[tid] = x1 * inv;
        eS[tid + 32] = x2 * inv;
    }
    __syncthreads();

    // context over fp16 feature; thread handles 2 channels (one half2)
    {
        const __half2* fb = g_feat_h2 + (size_t)b * (C_DIM / 2) + tid;
        float cx = 0.f, cy = 0.f;
        #pragma unroll 8
        for (int t = 0; t < T_DIM; t++) {
            float2 f = __half22float2(fb[(size_t)t * B_DIM * (C_DIM / 2)]);
            float a = eS[t];
            cx = fmaf(a, f.x, cx);
            cy = fmaf(a, f.y, cy);
        }
        *(float2*)(g_x + b * (C_DIM + E_DIM) + 2 * tid) = make_float2(cx, cy);
    }

    int tgt = (s == 0) ? 0 : g_text[b * S_DIM + (s - 1)];
    if (tid < E_DIM)
        g_x[b * (C_DIM + E_DIM) + C_DIM + tid] = char_emb[tgt * E_DIM + tid];
}

// ---------------- GRU cell ----------------------------------------------------
__global__ void gru_kernel(int s)
{
    int i = blockIdx.x * blockDim.x + threadIdx.x;
    int b = i >> 9, n = i & 511;

    const float* gib = g_gi + b * 1536;
    const float* ghb = g_hpgh + b * 2048 + 512;

    float ir = gib[n], iz = gib[512 + n], in = gib[1024 + n];
    float hr = ghb[n], hz = ghb[512 + n], hn = ghb[1024 + n];
    float h = g_hidden[i];

    float r = 1.f / (1.f + expf(-(ir + hr)));
    float z = 1.f / (1.f + expf(-(iz + hz)));
    float nn = tanhf(in + r * hn);
    float hN = (1.f - z) * nn + z * h;

    g_hidden[i] = hN;
    g_hs[((size_t)b * S_DIM + s) * H_DIM + n] = hN;
}

// ---------------- host ---------------------------------------------------------
struct Ptrs {
    float *hpgh, *x, *gi, *hidden, *hs;
    __half2 *fproj_h2, *feat_h2;
    float *whpgh_hi, *whpgh_lo, *wih_hi, *wih_lo, *wc2h_hi, *wc2h_lo, *wgen_hi, *wgen_lo;
    float *bias_hpgh;
};

extern "C" void kernel_launch(void* const* d_in, const int* in_sizes, int n_in,
                              void* d_out, int out_size)
{
    (void)in_sizes; (void)n_in; (void)out_size;
    const float* feature  = (const float*)d_in[0];
    const int*   text_raw = (const int*)  d_in[1];
    const float* W_h2h    = (const float*)d_in[2];
    const float* b_h2h    = (const float*)d_in[3];
    const float* W_c2h    = (const float*)d_in[4];
    const float* W_score  = (const float*)d_in[5];
    const float* W_ih     = (const float*)d_in[6];
    const float* W_hh     = (const float*)d_in[7];
    const float* b_ih     = (const float*)d_in[8];
    const float* b_hh     = (const float*)d_in[9];
    const float* char_emb = (const float*)d_in[10];
    const float* W_gen    = (const float*)d_in[11];
    const float* b_gen    = (const float*)d_in[12];
    float* out = (float*)d_out;

    constexpr int SMEM_128 = 320 * (128 + 128);  // 81920
    constexpr int SMEM_64  = 320 * (64 + 128);   // 61440

    static Ptrs P = [] {
        Ptrs p;
        cudaGetSymbolAddress((void**)&p.hpgh,     g_hpgh);
        cudaGetSymbolAddress((void**)&p.x,        g_x);
        cudaGetSymbolAddress((void**)&p.gi,       g_gi);
        cudaGetSymbolAddress((void**)&p.hidden,   g_hidden);
        cudaGetSymbolAddress((void**)&p.hs,       g_hs);
        cudaGetSymbolAddress((void**)&p.fproj_h2, g_fproj_h2);
        cudaGetSymbolAddress((void**)&p.feat_h2,  g_feat_h2);
        cudaGetSymbolAddress((void**)&p.whpgh_hi, g_Whpgh_hi);
        cudaGetSymbolAddress((void**)&p.whpgh_lo, g_Whpgh_lo);
        cudaGetSymbolAddress((void**)&p.wih_hi,   g_Wih_hi);
        cudaGetSymbolAddress((void**)&p.wih_lo,   g_Wih_lo);
        cudaGetSymbolAddress((void**)&p.wc2h_hi,  g_Wc2h_hi);
        cudaGetSymbolAddress((void**)&p.wc2h_lo,  g_Wc2h_lo);
        cudaGetSymbolAddress((void**)&p.wgen_hi,  g_Wgen_hi);
        cudaGetSymbolAddress((void**)&p.wgen_lo,  g_Wgen_lo);
        cudaGetSymbolAddress((void**)&p.bias_hpgh, g_bias_hpgh);
        cudaFuncSetAttribute(gemm_tf32<128, 128, 32, 64, 1>,
                             cudaFuncAttributeMaxDynamicSharedMemorySize, SMEM_128);
        cudaFuncSetAttribute(gemm_tf32<128, 128, 32, 64, 0>,
                             cudaFuncAttributeMaxDynamicSharedMemorySize, SMEM_128);
        cudaFuncSetAttribute(gemm_tf32<64, 128, 32, 32, 0>,
                             cudaFuncAttributeMaxDynamicSharedMemorySize, SMEM_64);
        return p;
    }();

    // ---- one-time-per-launch prep ----
    textnorm_kernel<<<1, 256>>>(text_raw);
    cudaMemsetAsync(P.hidden, 0, B_DIM * H_DIM * sizeof(float));

    // fp16 copy of feature
    {
        int n2 = T_DIM * B_DIM * C_DIM / 2;
        tohalf_k<<<(n2 + 255) / 256, 256>>>(feature, P.feat_h2, n2);
    }
    // weight splits
    presplit_k<<<(512 * 512 + 255) / 256, 256>>>(W_h2h, P.whpgh_hi, P.whpgh_lo, 512 * 512);
    presplit_k<<<(1536 * 512 + 255) / 256, 256>>>(W_hh, P.whpgh_hi + 512 * 512,
                                                  P.whpgh_lo + 512 * 512, 1536 * 512);
    presplit_k<<<(1536 * 640 + 255) / 256, 256>>>(W_ih, P.wih_hi, P.wih_lo, 1536 * 640);
    presplit_k<<<(512 * 512 + 255) / 256, 256>>>(W_c2h, P.wc2h_hi, P.wc2h_lo, 512 * 512);
    presplit_pad_k<<<(128 * 512 + 255) / 256, 256>>>(W_gen, P.wgen_hi, P.wgen_lo,
                                                     96 * 512, 128 * 512);
    cudaMemcpyAsync(P.bias_hpgh, b_h2h, 512 * sizeof(float), cudaMemcpyDeviceToDevice);
    cudaMemcpyAsync(P.bias_hpgh + 512, b_hh, 1536 * sizeof(float), cudaMemcpyDeviceToDevice);

    // fproj = feature @ W_c2h^T  -> fp16   (M=32768, N=512, K=512)
    gemm_tf32<128, 128, 32, 64, 1><<<dim3(4, 256), 256, SMEM_128>>>(
        feature, P.wc2h_hi, P.wc2h_lo, nullptr, P.fproj_h2, T_DIM * B_DIM, H_DIM, C_DIM);

    for (int s = 0; s < S_DIM; s++) {
        // [hp | gh] = hidden @ [W_h2h; W_hh]^T + bias  (512 x 2048 x 512)
        gemm_tf32<64, 128, 32, 32, 0><<<dim3(16, 8), 256, SMEM_64>>>(
            P.hidden, P.whpgh_hi, P.whpgh_lo, P.bias_hpgh, P.hpgh, B_DIM, 2048, H_DIM);

        att_kernel<<<B_DIM, 256>>>(W_score, char_emb, s);

        // gi = x @ W_ih^T + b_ih  (512 x 1536 x 640)
        gemm_tf32<64, 128, 32, 32, 0><<<dim3(12, 8), 256, SMEM_64>>>(
            P.x, P.wih_hi, P.wih_lo, b_ih, P.gi, B_DIM, 3 * H_DIM, C_DIM + E_DIM);

        gru_kernel<<<(B_DIM * H_DIM) / 256, 256>>>(s);
    }

    // probs = hs @ W_gen^T + b_gen  (16384 x 96 x 512)
    gemm_tf32<128, 128, 32, 64, 0><<<dim3(1, 128), 256, SMEM_128>>>(
        P.hs, P.wgen_hi, P.wgen_lo, b_gen, out, B_DIM * S_DIM, NC_DIM, H_DIM);
}

// round 4
// speedup vs baseline: 2.3654x; 1.5519x over previous
#include <cuda_runtime.h>
#include <cuda_fp16.h>
#include <cstdint>
#include <cstddef>

#define T_DIM 64
#define B_DIM 512
#define C_DIM 512
#define H_DIM 512
#define E_DIM 128
#define NC_DIM 96
#define S_DIM 32

// Weight row layout inside the packed fp16 hi/lo arrays (all K=512):
//  rows [0,2048)    : [W_h2h ; W_hh]   (hpgh GEMM)
//  rows [2048,3584) : W_ih[:, 0:512]   (gi GEMM)
//  rows [3584,3712) : W_gen padded 96->128
//  rows [3712,4224) : W_c2h            (fproj GEMM)
#define WROWS 4224
#define OFF_IH  (2048 * 512)
#define OFF_GEN (3584 * 512)
#define OFF_C2H (3712 * 512)

// ---------------- scratch (device globals) ----------------------------------
__device__ __half2 g_fproj_h2[(size_t)T_DIM * B_DIM * (H_DIM / 2)];
__device__ __half2 g_feat_h2[(size_t)T_DIM * B_DIM * (C_DIM / 2)];
__device__ __half  g_Whi[(size_t)WROWS * 512];
__device__ __half  g_Wlo[(size_t)WROWS * 512];
__device__ float   g_embtab[96 * 1536];
__device__ float   g_hpgh[B_DIM * 2048];     // [B][ hp(512) | hr hz hn (3*512) ]
__device__ float   g_x[B_DIM * 512];
__device__ float   g_hidden[B_DIM * 512];
__device__ float   g_hs[(size_t)S_DIM * B_DIM * 512];   // rows (b*S+s)
__device__ int     g_text[B_DIM * S_DIM];
__device__ float   g_bias_hpgh[2048];

// ---------------- fast math helpers ------------------------------------------
__device__ __forceinline__ float sigf(float x) {
    return __fdividef(1.f, 1.f + __expf(-x));
}
__device__ __forceinline__ float tanhf_fast(float x) {
    x = fminf(fmaxf(x, -15.f), 15.f);
    float e = __expf(-2.f * x);
    return __fdividef(1.f - e, 1.f + e);
}

// ---------------- mma / ldmatrix helpers --------------------------------------
__device__ __forceinline__ void ldsm4(uint32_t& r0, uint32_t& r1, uint32_t& r2,
                                      uint32_t& r3, uint32_t a) {
    asm volatile("ldmatrix.sync.aligned.m8n8.x4.shared.b16 {%0,%1,%2,%3}, [%4];"
                 : "=r"(r0), "=r"(r1), "=r"(r2), "=r"(r3) : "r"(a));
}
__device__ __forceinline__ void mma16816(float* d, const uint32_t* a, uint32_t b0, uint32_t b1) {
    asm volatile("mma.sync.aligned.m16n8k16.row.col.f32.f16.f16.f32 "
                 "{%0,%1,%2,%3},{%4,%5,%6,%7},{%8,%9},{%0,%1,%2,%3};"
                 : "+f"(d[0]), "+f"(d[1]), "+f"(d[2]), "+f"(d[3])
                 : "r"(a[0]), "r"(a[1]), "r"(a[2]), "r"(a[3]), "r"(b0), "r"(b1));
}

// ---------------- text dtype normalization ------------------------------------
__global__ void textnorm_kernel(const int* __restrict__ raw) {
    __shared__ int is32;
    int tid = threadIdx.x;
    if (tid == 0) is32 = 0;
    __syncthreads();
    int local = 0;
    for (int i = tid; i < 8192; i += blockDim.x) local |= raw[2 * i + 1];
    if (local) atomicOr(&is32, 1);
    __syncthreads();
    if (is32) {
        for (int i = tid; i < B_DIM * S_DIM; i += blockDim.x) g_text[i] = raw[i];
    } else {
        for (int i = tid; i < B_DIM * S_DIM; i += blockDim.x) g_text[i] = raw[2 * i];
    }
}

// ---------------- one-time transforms ------------------------------------------
__global__ void tohalf_k(const float* __restrict__ src, __half2* __restrict__ dst, int n2) {
    int i = blockIdx.x * blockDim.x + threadIdx.x;
    if (i < n2) {
        float2 v = ((const float2*)src)[i];
        dst[i] = __floats2half2_rn(v.x, v.y);
    }
}

__global__ void presplit_all(const float* __restrict__ W_h2h, const float* __restrict__ W_hh,
                             const float* __restrict__ W_ih, const float* __restrict__ W_gen,
                             const float* __restrict__ W_c2h) {
    int idx = blockIdx.x * 256 + threadIdx.x;
    if (idx >= WROWS * 512) return;
    int row = idx >> 9, k = idx & 511;
    float v;
    if (row < 512)        v = W_h2h[row * 512 + k];
    else if (row < 2048)  v = W_hh[(row - 512) * 512 + k];
    else if (row < 3584)  v = W_ih[(size_t)(row - 2048) * 640 + k];
    else if (row < 3712) { int r = row - 3584; v = (r < 96) ? W_gen[r * 512 + k] : 0.f; }
    else                  v = W_c2h[(row - 3712) * 512 + k];
    __half h = __float2half_rn(v);
    g_Whi[idx] = h;
    g_Wlo[idx] = __float2half_rn(v - __half2float(h));
}

// embtab[t][n] = sum_j char_emb[t][j] * W_ih[n][512+j]   (fp32, exact)
__global__ void embtab_k(const float* __restrict__ char_emb, const float* __restrict__ W_ih) {
    int t = blockIdx.y;
    int n = blockIdx.x * 256 + threadIdx.x;
    __shared__ float e[128];
    if (threadIdx.x < 128) e[threadIdx.x] = char_emb[t * 128 + threadIdx.x];
    __syncthreads();
    const float* w = W_ih + (size_t)n * 640 + 512;
    float acc = 0.f;
    #pragma unroll
    for (int j = 0; j < 128; j++) acc = fmaf(e[j], w[j], acc);
    g_embtab[t * 1536 + n] = acc;
}

// ---------------- fp16-split tensor-core GEMM ----------------------------------
// C[M, N] = A[M,512] @ W[N,512]^T (+bias). NPASS=3: a,w split hi/lo (err ~2^-22).
// MODE 0: fp32 out + bias (ldc=NL, store guard n<NL)
// MODE 1: fp16 out (ldc=512)
// MODE 2: NCHUNK=3 gi+GRU fused epilogue
template<int BM, int BN, int NCHUNK, int NPASS, int MODE>
__global__ void __launch_bounds__(256, 1)
gemm_f16(const float* __restrict__ A,
         const __half* __restrict__ Whi, const __half* __restrict__ Wlo,
         const float* __restrict__ bias, void* __restrict__ Cout,
         int NL, int s)
{
    constexpr int LD = 40;          // fp16 stride: 80B row, conflict-free ldmatrix
    constexpr int BNR = BN * NCHUNK;
    constexpr int KT = 16;          // K = 512, BK = 32
    constexpr int WM = BM / 2, WN = BN / 4;
    constexpr int MT = WM / 16, NT = WN / 8, NG = NT / 2;
    constexpr int A_F4 = BM / 32;
    constexpr int W_F4 = BNR / 64;
    constexpr int ASZ = BM * LD;
    constexpr int BSZ = BNR * LD;

    extern __shared__ __half sh[];
    __half* Ahi = sh;
    __half* Alo = Ahi + 2 * ASZ;
    __half* Bhi = (NPASS == 3) ? (Alo + 2 * ASZ) : (Ahi + 2 * ASZ);
    __half* Blo = Bhi + 2 * BSZ;

    const int tid = threadIdx.x;
    const int warp = tid >> 5, lane = tid & 31;
    const int g = lane >> 2, c = lane & 3;
    const int wm = warp & 1, wn = warp >> 1;
    const int m0 = blockIdx.y * BM, n0 = blockIdx.x * BN;
    const int lr = lane & 15, lc2 = (lane >> 4) << 3;

    const uint32_t sAh = (uint32_t)__cvta_generic_to_shared(Ahi);
    const uint32_t sAl = (uint32_t)__cvta_generic_to_shared(Alo);
    const uint32_t sBh = (uint32_t)__cvta_generic_to_shared(Bhi);
    const uint32_t sBl = (uint32_t)__cvta_generic_to_shared(Blo);

    float acc[NCHUNK][MT][NT][4];
    #pragma unroll
    for (int ch = 0; ch < NCHUNK; ch++)
        #pragma unroll
        for (int i = 0; i < MT; i++)
            #pragma unroll
            for (int j = 0; j < NT; j++)
                #pragma unroll
                for (int q = 0; q < 4; q++) acc[ch][i][j][q] = 0.f;

    float4 pa[A_F4];
    uint4 ph[W_F4], pl[W_F4];

    auto loadS = [&](int kt) {
        #pragma unroll
        for (int i = 0; i < A_F4; i++) {
            int idx = i * 256 + tid, r = idx >> 3, kq = (idx & 7) << 2;
            pa[i] = *(const float4*)(A + (size_t)(m0 + r) * 512 + kt * 32 + kq);
        }
        #pragma unroll
        for (int i = 0; i < W_F4; i++) {
            int idx = i * 256 + tid, r = idx >> 2, q = idx & 3;
            int ch = r / BN;
            int row = ch * 512 + n0 + (r - ch * BN);
            size_t off = (size_t)row * 512 + kt * 32 + q * 8;
            ph[i] = *(const uint4*)(Whi + off);
            if constexpr (NPASS == 3) pl[i] = *(const uint4*)(Wlo + off);
        }
    };
    auto storeS = [&](int buf) {
        #pragma unroll
        for (int i = 0; i < A_F4; i++) {
            int idx = i * 256 + tid, r = idx >> 3, kq = (idx & 7) << 2;
            float4 v = pa[i];
            __half h0 = __float2half_rn(v.x), h1 = __float2half_rn(v.y);
            __half h2 = __float2half_rn(v.z), h3 = __float2half_rn(v.w);
            __half2* d = (__half2*)(Ahi + buf * ASZ + r * LD + kq);
            d[0] = __halves2half2(h0, h1);
            d[1] = __halves2half2(h2, h3);
            if constexpr (NPASS == 3) {
                __half l0 = __float2half_rn(v.x - __half2float(h0));
                __half l1 = __float2half_rn(v.y - __half2float(h1));
                __half l2 = __float2half_rn(v.z - __half2float(h2));
                __half l3 = __float2half_rn(v.w - __half2float(h3));
                __half2* dl = (__half2*)(Alo + buf * ASZ + r * LD + kq);
                dl[0] = __halves2half2(l0, l1);
                dl[1] = __halves2half2(l2, l3);
            }
        }
        #pragma unroll
        for (int i = 0; i < W_F4; i++) {
            int idx = i * 256 + tid, r = idx >> 2, q = idx & 3;
            *(uint4*)(Bhi + buf * BSZ + r * LD + q * 8) = ph[i];
            if constexpr (NPASS == 3) *(uint4*)(Blo + buf * BSZ + r * LD + q * 8) = pl[i];
        }
    };

    loadS(0); storeS(0);
    __syncthreads();

    int buf = 0;
    for (int kt = 0; kt < KT; kt++) {
        if (kt + 1 < KT) loadS(kt + 1);
        const uint32_t aOH = sAh + buf * ASZ * 2;
        const uint32_t aOL = sAl + buf * ASZ * 2;
        const uint32_t bOH = sBh + buf * BSZ * 2;
        const uint32_t bOL = sBl + buf * BSZ * 2;

        #pragma unroll
        for (int k16 = 0; k16 < 32; k16 += 16) {
            uint32_t aH[MT][4], aL[MT][4];
            #pragma unroll
            for (int mt = 0; mt < MT; mt++) {
                int mrow = wm * WM + mt * 16 + lr;
                ldsm4(aH[mt][0], aH[mt][1], aH[mt][2], aH[mt][3],
                      aOH + (mrow * LD + k16 + lc2) * 2);
                if constexpr (NPASS == 3)
                    ldsm4(aL[mt][0], aL[mt][1], aL[mt][2], aL[mt][3],
                          aOL + (mrow * LD + k16 + lc2) * 2);
            }
            #pragma unroll
            for (int ch = 0; ch < NCHUNK; ch++) {
                #pragma unroll
                for (int g2 = 0; g2 < NG; g2++) {
                    int nb = ch * BN + wn * WN + g2 * 16 + lr;
                    // W stored [N][K] row-major -> B fragment needs NON-trans
                    // ldmatrix (lane holds 2 consecutive k at fixed n).
                    uint32_t b0, b1, b2, b3;
                    ldsm4(b0, b1, b2, b3, bOH + (nb * LD + k16 + lc2) * 2);
                    #pragma unroll
                    for (int mt = 0; mt < MT; mt++) {
                        mma16816(acc[ch][mt][2 * g2],     aH[mt], b0, b2);
                        mma16816(acc[ch][mt][2 * g2 + 1], aH[mt], b1, b3);
                    }
                    if constexpr (NPASS == 3) {
                        #pragma unroll
                        for (int mt = 0; mt < MT; mt++) {
                            mma16816(acc[ch][mt][2 * g2],     aL[mt], b0, b2);
                            mma16816(acc[ch][mt][2 * g2 + 1], aL[mt], b1, b3);
                        }
                        uint32_t l0, l1, l2, l3;
                        ldsm4(l0, l1, l2, l3, bOL + (nb * LD + k16 + lc2) * 2);
                        #pragma unroll
                        for (int mt = 0; mt < MT; mt++) {
                            mma16816(acc[ch][mt][2 * g2],     aH[mt], l0, l2);
                            mma16816(acc[ch][mt][2 * g2 + 1], aH[mt], l1, l3);
                        }
                    }
                }
            }
        }
        if (kt + 1 < KT) storeS(buf ^ 1);
        __syncthreads();
        buf ^= 1;
    }

    // ---------------- epilogues ----------------
    if constexpr (MODE == 0) {
        float* Cf = (float*)Cout;
        #pragma unroll
        for (int mt = 0; mt < MT; mt++) {
            #pragma unroll
            for (int nt = 0; nt < NT; nt++) {
                int m = m0 + wm * WM + mt * 16 + g;
                int n = n0 + wn * WN + nt * 8 + 2 * c;
                if (n < NL) {
                    float b0 = bias ? bias[n] : 0.f;
                    float b1 = bias ? bias[n + 1] : 0.f;
                    *(float2*)(Cf + (size_t)m * NL + n) =
                        make_float2(acc[0][mt][nt][0] + b0, acc[0][mt][nt][1] + b1);
                    *(float2*)(Cf + (size_t)(m + 8) * NL + n) =
                        make_float2(acc[0][mt][nt][2] + b0, acc[0][mt][nt][3] + b1);
                }
            }
        }
    } else if constexpr (MODE == 1) {
        __half2* Ch = (__half2*)Cout;
        #pragma unroll
        for (int mt = 0; mt < MT; mt++) {
            #pragma unroll
            for (int nt = 0; nt < NT; nt++) {
                int m = m0 + wm * WM + mt * 16 + g;
                int n = n0 + wn * WN + nt * 8 + 2 * c;
                Ch[((size_t)m * 512 + n) >> 1] =
                    __floats2half2_rn(acc[0][mt][nt][0], acc[0][mt][nt][1]);
                Ch[((size_t)(m + 8) * 512 + n) >> 1] =
                    __floats2half2_rn(acc[0][mt][nt][2], acc[0][mt][nt][3]);
            }
        }
    } else {  // MODE 2: GRU fused epilogue
        #pragma unroll
        for (int mt = 0; mt < MT; mt++) {
            #pragma unroll
            for (int rowh = 0; rowh < 2; rowh++) {
                int b = m0 + wm * WM + mt * 16 + g + rowh * 8;
                int tg = (s == 0) ? 0 : g_text[b * S_DIM + s - 1];
                #pragma unroll
                for (int nt = 0; nt < NT; nt++) {
                    int n = n0 + wn * WN + nt * 8 + 2 * c;
                    int q = rowh * 2;
                    float arx = acc[0][mt][nt][q], ary = acc[0][mt][nt][q + 1];
                    float azx = acc[1][mt][nt][q], azy = acc[1][mt][nt][q + 1];
                    float anx = acc[2][mt][nt][q], any_ = acc[2][mt][nt][q + 1];
                    float2 hr = *(const float2*)&g_hpgh[b * 2048 + 512 + n];
                    float2 hz = *(const float2*)&g_hpgh[b * 2048 + 1024 + n];
                    float2 hn = *(const float2*)&g_hpgh[b * 2048 + 1536 + n];
                    float2 er = *(const float2*)&g_embtab[tg * 1536 + n];
                    float2 ez = *(const float2*)&g_embtab[tg * 1536 + 512 + n];
                    float2 en = *(const float2*)&g_embtab[tg * 1536 + 1024 + n];
                    float2 br = *(const float2*)&bias[n];
                    float2 bz = *(const float2*)&bias[512 + n];
                    float2 bn = *(const float2*)&bias[1024 + n];
                    float2 h  = *(const float2*)&g_hidden[b * 512 + n];
                    float rx = sigf(arx + br.x + er.x + hr.x);
                    float ry = sigf(ary + br.y + er.y + hr.y);
                    float zx = sigf(azx + bz.x + ez.x + hz.x);
                    float zy = sigf(azy + bz.y + ez.y + hz.y);
                    float nx = tanhf_fast(anx + bn.x + en.x + rx * hn.x);
                    float ny = tanhf_fast(any_ + bn.y + en.y + ry * hn.y);
                    float hx = (1.f - zx) * nx + zx * h.x;
                    float hy = (1.f - zy) * ny + zy * h.y;
                    *(float2*)&g_hidden[b * 512 + n] = make_float2(hx, hy);
                    *(float2*)&g_hs[((size_t)b * S_DIM + s) * 512 + n] = make_float2(hx, hy);
                }
            }
        }
    }
}

// ---------------- fused attention ----------------------------------------------
__global__ void att_kernel(const float* __restrict__ Wscore) {
    __shared__ float hpS[H_DIM];
    __shared__ float wS[H_DIM];
    __shared__ float eS[T_DIM];

    const int b = blockIdx.x;
    const int tid = threadIdx.x;
    const int warp = tid >> 5, lane = tid & 31;

    for (int h = tid; h < H_DIM; h += 256) {
        hpS[h] = g_hpgh[b * 2048 + h];
        wS[h] = Wscore[h];
    }
    __syncthreads();

    for (int t = warp; t < T_DIM; t += 8) {
        const __half2* fp = g_fproj_h2 + ((size_t)t * B_DIM + b) * (H_DIM / 2);
        float p = 0.f;
        #pragma unroll 4
        for (int i = lane; i < H_DIM / 2; i += 32) {
            float2 f = __half22float2(fp[i]);
            p += tanhf_fast(f.x + hpS[2 * i]) * wS[2 * i];
            p += tanhf_fast(f.y + hpS[2 * i + 1]) * wS[2 * i + 1];
        }
        #pragma unroll
        for (int off = 16; off; off >>= 1) p += __shfl_xor_sync(0xFFFFFFFFu, p, off);
        if (lane == 0) eS[t] = p;
    }
    __syncthreads();

    if (tid < 32) {
        float e1 = eS[tid], e2 = eS[tid + 32];
        float m = fmaxf(e1, e2);
        #pragma unroll
        for (int off = 16; off; off >>= 1) m = fmaxf(m, __shfl_xor_sync(0xFFFFFFFFu, m, off));
        float x1 = __expf(e1 - m), x2 = __expf(e2 - m);
        float ssum = x1 + x2;
        #pragma unroll
        for (int off = 16; off; off >>= 1) ssum += __shfl_xor_sync(0xFFFFFFFFu, ssum, off);
        float inv = __fdividef(1.f, ssum);
        eS[tid] = x1 * inv;
        eS[tid + 32] = x2 * inv;
    }
    __syncthreads();

    {
        const __half2* fb = g_feat_h2 + (size_t)b * (C_DIM / 2) + tid;
        float cx = 0.f, cy = 0.f;
        #pragma unroll 8
        for (int t = 0; t < T_DIM; t++) {
            float2 f = __half22float2(fb[(size_t)t * B_DIM * (C_DIM / 2)]);
            float a = eS[t];
            cx = fmaf(a, f.x, cx);
            cy = fmaf(a, f.y, cy);
        }
        *(float2*)(g_x + b * 512 + 2 * tid) = make_float2(cx, cy);
    }
}

// ---------------- host ----------------------------------------------------------
struct Ptrs {
    float *hpgh, *x, *hidden, *hs, *bias_hpgh;
    __half2 *fproj_h2, *feat_h2;
    __half *whi, *wlo;
};

constexpr int SMEM_HPGH = 2 * 2 * 40 * (64 * 2 + 128 * 2);   // 61440
constexpr int SMEM_FP   = 2 * 2 * 40 * (128 + 128);          // 40960
constexpr int SMEM_GRU  = 2 * 2 * 40 * (64 * 2 + 192 * 2);   // 81920

extern "C" void kernel_launch(void* const* d_in, const int* in_sizes, int n_in,
                              void* d_out, int out_size)
{
    (void)in_sizes; (void)n_in; (void)out_size;
    const float* feature  = (const float*)d_in[0];
    const int*   text_raw = (const int*)  d_in[1];
    const float* W_h2h    = (const float*)d_in[2];
    const float* b_h2h    = (const float*)d_in[3];
    const float* W_c2h    = (const float*)d_in[4];
    const float* W_score  = (const float*)d_in[5];
    const float* W_ih     = (const float*)d_in[6];
    const float* W_hh     = (const float*)d_in[7];
    const float* b_ih     = (const float*)d_in[8];
    const float* b_hh     = (const float*)d_in[9];
    const float* char_emb = (const float*)d_in[10];
    const float* W_gen    = (const float*)d_in[11];
    const float* b_gen    = (const float*)d_in[12];
    float* out = (float*)d_out;

    static Ptrs P = [] {
        Ptrs p;
        cudaGetSymbolAddress((void**)&p.hpgh,      g_hpgh);
        cudaGetSymbolAddress((void**)&p.x,         g_x);
        cudaGetSymbolAddress((void**)&p.hidden,    g_hidden);
        cudaGetSymbolAddress((void**)&p.hs,        g_hs);
        cudaGetSymbolAddress((void**)&p.bias_hpgh, g_bias_hpgh);
        cudaGetSymbolAddress((void**)&p.fproj_h2,  g_fproj_h2);
        cudaGetSymbolAddress((void**)&p.feat_h2,   g_feat_h2);
        cudaGetSymbolAddress((void**)&p.whi,       g_Whi);
        cudaGetSymbolAddress((void**)&p.wlo,       g_Wlo);
        cudaFuncSetAttribute(gemm_f16<64, 128, 1, 3, 0>,
                             cudaFuncAttributeMaxDynamicSharedMemorySize, SMEM_HPGH);
        cudaFuncSetAttribute(gemm_f16<128, 128, 1, 1, 1>,
                             cudaFuncAttributeMaxDynamicSharedMemorySize, SMEM_FP);
        cudaFuncSetAttribute(gemm_f16<64, 64, 3, 3, 2>,
                             cudaFuncAttributeMaxDynamicSharedMemorySize, SMEM_GRU);
        return p;
    }();

    // ---- prep
    textnorm_kernel<<<1, 256>>>(text_raw);
    {
        int n2 = T_DIM * B_DIM * C_DIM / 2;
        tohalf_k<<<(n2 + 255) / 256, 256>>>(feature, P.feat_h2, n2);
    }
    presplit_all<<<(WROWS * 512 + 255) / 256, 256>>>(W_h2h, W_hh, W_ih,
                                                     W_gen, W_c2h);
    embtab_k<<<dim3(6, 96), 256>>>(char_emb, W_ih);

    cudaMemsetAsync(P.hidden, 0, B_DIM * 512 * sizeof(float));
    cudaMemcpyAsync(P.bias_hpgh, b_h2h, 512 * sizeof(float), cudaMemcpyDeviceToDevice);
    cudaMemcpyAsync(P.bias_hpgh + 512, b_hh, 1536 * sizeof(float), cudaMemcpyDeviceToDevice);

    // fproj = feature @ W_c2h^T -> fp16  (M=32768, N=512) single-pass
    gemm_f16<128, 128, 1, 1, 1><<<dim3(4, 256), 256, SMEM_FP>>>(
        feature, P.whi + OFF_C2H, P.wlo + OFF_C2H, nullptr,
        P.fproj_h2, 512, 0);

    for (int s = 0; s < S_DIM; s++) {
        // [hp | hr hz hn] = hidden @ [W_h2h; W_hh]^T + bias  (512 x 2048)
        gemm_f16<64, 128, 1, 3, 0><<<dim3(16, 8), 256, SMEM_HPGH>>>(
            P.hidden, P.whi, P.wlo, P.bias_hpgh, P.hpgh, 2048, s);

        att_kernel<<<B_DIM, 256>>>(W_score);

        // gi (3 gate chunks over n in [0,512)) + GRU epilogue
        gemm_f16<64, 64, 3, 3, 2><<<dim3(8, 8), 256, SMEM_GRU>>>(
            P.x, P.whi + OFF_IH, P.wlo + OFF_IH, b_ih, nullptr, 512, s);
    }

    // probs = hs @ W_gen^T + b_gen  (16384 x 96), W padded to 128 rows
    gemm_f16<64, 128, 1, 3, 0><<<dim3(1, 256), 256, SMEM_HPGH>>>(
        P.hs, P.whi + OFF_GEN, P.wlo + OFF_GEN, b_gen, out, 96, 0);
}

// round 6
// speedup vs baseline: 3.9212x; 1.6577x over previous
#include <cuda_runtime.h>
#include <cuda_fp16.h>
#include <cstdint>
#include <cstddef>

#define T_DIM 64
#define B_DIM 512
#define C_DIM 512
#define H_DIM 512
#define E_DIM 128
#define NC_DIM 96
#define S_DIM 32

// Weight row layout inside the packed fp16 hi/lo arrays (all K=512):
//  rows [0,2048)    : [W_h2h ; W_hh]   (hpgh GEMM)
//  rows [2048,3584) : W_ih[:, 0:512]   (gi GEMM)
//  rows [3584,3712) : W_gen padded 96->128
//  rows [3712,4224) : W_c2h            (fproj GEMM)
#define WROWS 4224
#define OFF_IH  (2048 * 512)
#define OFF_GEN (3584 * 512)
#define OFF_C2H (3712 * 512)

// ---------------- scratch (device globals) ----------------------------------
__device__ __half2 g_fproj_h2[(size_t)T_DIM * B_DIM * (H_DIM / 2)];
__device__ __half2 g_feat_h2[(size_t)T_DIM * B_DIM * (C_DIM / 2)];
__device__ __half  g_Whi[(size_t)WROWS * 512];
__device__ __half  g_Wlo[(size_t)WROWS * 512];
__device__ float   g_embtab[96 * 1536];
__device__ float   g_hpgh[B_DIM * 2048];     // [B][ hp(512) | hr hz hn (3*512) ]
__device__ float   g_x[B_DIM * 512];
__device__ float   g_hidden[B_DIM * 512];
__device__ float   g_hs[(size_t)S_DIM * B_DIM * 512];   // rows (b*S+s)
__device__ int     g_text[B_DIM * S_DIM];
__device__ float   g_bias_hpgh[2048];

// ---------------- fast math helpers ------------------------------------------
__device__ __forceinline__ float sigf(float x) {
    return __fdividef(1.f, 1.f + __expf(-x));
}
__device__ __forceinline__ float tanhf_fast(float x) {
    x = fminf(fmaxf(x, -15.f), 15.f);
    float e = __expf(-2.f * x);
    return __fdividef(1.f - e, 1.f + e);
}
__device__ __forceinline__ float tanh_mufu(float x) {
    float y;
    asm("tanh.approx.f32 %0, %1;" : "=f"(y) : "f"(x));
    return y;
}

// ---------------- mma / ldmatrix helpers --------------------------------------
__device__ __forceinline__ void ldsm4(uint32_t& r0, uint32_t& r1, uint32_t& r2,
                                      uint32_t& r3, uint32_t a) {
    asm volatile("ldmatrix.sync.aligned.m8n8.x4.shared.b16 {%0,%1,%2,%3}, [%4];"
                 : "=r"(r0), "=r"(r1), "=r"(r2), "=r"(r3) : "r"(a));
}
__device__ __forceinline__ void mma16816(float* d, const uint32_t* a, uint32_t b0, uint32_t b1) {
    asm volatile("mma.sync.aligned.m16n8k16.row.col.f32.f16.f16.f32 "
                 "{%0,%1,%2,%3},{%4,%5,%6,%7},{%8,%9},{%0,%1,%2,%3};"
                 : "+f"(d[0]), "+f"(d[1]), "+f"(d[2]), "+f"(d[3])
                 : "r"(a[0]), "r"(a[1]), "r"(a[2]), "r"(a[3]), "r"(b0), "r"(b1));
}

// ---------------- text dtype normalization ------------------------------------
__global__ void textnorm_kernel(const int* __restrict__ raw) {
    __shared__ int is32;
    int tid = threadIdx.x;
    if (tid == 0) is32 = 0;
    __syncthreads();
    int local = 0;
    for (int i = tid; i < 8192; i += blockDim.x) local |= raw[2 * i + 1];
    if (local) atomicOr(&is32, 1);
    __syncthreads();
    if (is32) {
        for (int i = tid; i < B_DIM * S_DIM; i += blockDim.x) g_text[i] = raw[i];
    } else {
        for (int i = tid; i < B_DIM * S_DIM; i += blockDim.x) g_text[i] = raw[2 * i];
    }
}

// ---------------- one-time transforms ------------------------------------------
// fp16 copy of feature + zero g_hidden (folded in to keep launch count fixed)
__global__ void tohalf_k(const float* __restrict__ src, __half2* __restrict__ dst, int n2) {
    int i = blockIdx.x * blockDim.x + threadIdx.x;
    if (i < n2) {
        float2 v = ((const float2*)src)[i];
        dst[i] = __floats2half2_rn(v.x, v.y);
    }
    if (i < B_DIM * 512 / 2) ((float2*)g_hidden)[i] = make_float2(0.f, 0.f);
}

__global__ void presplit_all(const float* __restrict__ W_h2h, const float* __restrict__ W_hh,
                             const float* __restrict__ W_ih, const float* __restrict__ W_gen,
                             const float* __restrict__ W_c2h,
                             const float* __restrict__ b_h2h, const float* __restrict__ b_hh) {
    int idx = blockIdx.x * 256 + threadIdx.x;
    if (idx >= WROWS * 512) return;
    if (idx < 2048)
        g_bias_hpgh[idx] = (idx < 512) ? b_h2h[idx] : b_hh[idx - 512];
    int row = idx >> 9, k = idx & 511;
    float v;
    if (row < 512)        v = W_h2h[row * 512 + k];
    else if (row < 2048)  v = W_hh[(row - 512) * 512 + k];
    else if (row < 3584)  v = W_ih[(size_t)(row - 2048) * 640 + k];
    else if (row < 3712) { int r = row - 3584; v = (r < 96) ? W_gen[r * 512 + k] : 0.f; }
    else                  v = W_c2h[(row - 3712) * 512 + k];
    __half h = __float2half_rn(v);
    g_Whi[idx] = h;
    g_Wlo[idx] = __float2half_rn(v - __half2float(h));
}

// embtab[t][n] = sum_j char_emb[t][j] * W_ih[n][512+j]  (fp32 exact, coalesced)
__global__ void embtab_k(const float* __restrict__ char_emb, const float* __restrict__ W_ih) {
    __shared__ float e[96][128];
    int tid = threadIdx.x;
    for (int i = tid; i < 96 * 128; i += 256)
        e[i >> 7][i & 127] = char_emb[i];
    __syncthreads();
    int warp = tid >> 5, lane = tid & 31;
    int n = blockIdx.x * 8 + warp;
    float4 wv = *(const float4*)(W_ih + (size_t)n * 640 + 512 + lane * 4);
    for (int t = 0; t < 96; t++) {
        float4 ev = *(const float4*)(&e[t][lane * 4]);
        float p = wv.x * ev.x + wv.y * ev.y + wv.z * ev.z + wv.w * ev.w;
        #pragma unroll
        for (int off = 16; off; off >>= 1) p += __shfl_xor_sync(0xFFFFFFFFu, p, off);
        if (lane == 0) g_embtab[t * 1536 + n] = p;
    }
}

// ---------------- fp16-split tensor-core GEMM ----------------------------------
// C[M, N] = A[M,512] @ W[N,512]^T (+bias).
// NPASS: 1 = aH*bH; 2 = (aH+aL)*bH; 3 = +aH*bL.
// MODE 0: fp32 out + bias (ldc=NL). MODE 1: fp16 out (ldc=512). MODE 2: gi+GRU fused.
// A16: A is fp16 (ld 512 halves), no split.
template<int BM, int BN, int NCHUNK, int NPASS, int MODE, int A16>
__global__ void __launch_bounds__(256, 1)
gemm_f16(const void* __restrict__ Ain,
         const __half* __restrict__ Whi, const __half* __restrict__ Wlo,
         const float* __restrict__ bias, void* __restrict__ Cout,
         int NL, int s)
{
    constexpr int LD = 40;          // fp16 row stride: 80B, conflict-free ldmatrix
    constexpr int BNR = BN * NCHUNK;
    constexpr int KT = 16;          // K = 512, BK = 32
    constexpr int WM = BM / 2, WN = BN / 4;
    constexpr int MT = WM / 16, NT = WN / 8, NG = NT / 2;
    static_assert(MT >= 1 && NG >= 1, "tile config");
    constexpr int ASZ = BM * LD;
    constexpr int BSZ = BNR * LD;
    constexpr int A_F4 = BM / 32;
    constexpr int A_H8 = (BM >= 64) ? BM / 64 : 1;
    constexpr int W_F4 = BNR / 64;

    extern __shared__ __half sh[];
    __half* Ahi = sh;
    __half* Alo = (NPASS >= 2) ? (Ahi + 2 * ASZ) : Ahi;
    __half* Bhi = Ahi + (NPASS >= 2 ? 4 : 2) * ASZ;
    __half* Blo = (NPASS == 3) ? (Bhi + 2 * BSZ) : Bhi;

    const int tid = threadIdx.x;
    const int warp = tid >> 5, lane = tid & 31;
    const int g = lane >> 2, c = lane & 3;
    const int wm = warp & 1, wn = warp >> 1;
    const int m0 = blockIdx.y * BM, n0 = blockIdx.x * BN;
    const int lr = lane & 15, lc2 = (lane >> 4) << 3;

    const uint32_t sAh = (uint32_t)__cvta_generic_to_shared(Ahi);
    const uint32_t sAl = (uint32_t)__cvta_generic_to_shared(Alo);
    const uint32_t sBh = (uint32_t)__cvta_generic_to_shared(Bhi);
    const uint32_t sBl = (uint32_t)__cvta_generic_to_shared(Blo);

    float acc[NCHUNK][MT][NT][4];
    #pragma unroll
    for (int ch = 0; ch < NCHUNK; ch++)
        #pragma unroll
        for (int i = 0; i < MT; i++)
            #pragma unroll
            for (int j = 0; j < NT; j++)
                #pragma unroll
                for (int q = 0; q < 4; q++) acc[ch][i][j][q] = 0.f;

    float4 pa[A16 ? 1 : A_F4];
    uint4 pah[A16 ? A_H8 : 1];
    uint4 ph[W_F4], pl[W_F4];

    auto loadS = [&](int kt) {
        if constexpr (A16) {
            const __half* Ah16 = (const __half*)Ain;
            #pragma unroll
            for (int i = 0; i < A_H8; i++) {
                int idx = i * 256 + tid, r = idx >> 2, q = idx & 3;
                pah[i] = *(const uint4*)(Ah16 + (size_t)(m0 + r) * 512 + kt * 32 + q * 8);
            }
        } else {
            const float* Af = (const float*)Ain;
            #pragma unroll
            for (int i = 0; i < A_F4; i++) {
                int idx = i * 256 + tid, r = idx >> 3, kq = (idx & 7) << 2;
                pa[i] = *(const float4*)(Af + (size_t)(m0 + r) * 512 + kt * 32 + kq);
            }
        }
        #pragma unroll
        for (int i = 0; i < W_F4; i++) {
            int idx = i * 256 + tid, r = idx >> 2, q = idx & 3;
            int ch = r / BN;
            int row = ch * 512 + n0 + (r - ch * BN);
            size_t off = (size_t)row * 512 + kt * 32 + q * 8;
            ph[i] = *(const uint4*)(Whi + off);
            if constexpr (NPASS == 3) pl[i] = *(const uint4*)(Wlo + off);
        }
    };
    auto storeS = [&](int buf) {
        if constexpr (A16) {
            #pragma unroll
            for (int i = 0; i < A_H8; i++) {
                int idx = i * 256 + tid, r = idx >> 2, q = idx & 3;
                *(uint4*)(Ahi + buf * ASZ + r * LD + q * 8) = pah[i];
            }
        } else {
            #pragma unroll
            for (int i = 0; i < A_F4; i++) {
                int idx = i * 256 + tid, r = idx >> 3, kq = (idx & 7) << 2;
                float4 v = pa[i];
                __half h0 = __float2half_rn(v.x), h1 = __float2half_rn(v.y);
                __half h2 = __float2half_rn(v.z), h3 = __float2half_rn(v.w);
                __half2* d = (__half2*)(Ahi + buf * ASZ + r * LD + kq);
                d[0] = __halves2half2(h0, h1);
                d[1] = __halves2half2(h2, h3);
                if constexpr (NPASS >= 2) {
                    __half l0 = __float2half_rn(v.x - __half2float(h0));
                    __half l1 = __float2half_rn(v.y - __half2float(h1));
                    __half l2 = __float2half_rn(v.z - __half2float(h2));
                    __half l3 = __float2half_rn(v.w - __half2float(h3));
                    __half2* dl = (__half2*)(Alo + buf * ASZ + r * LD + kq);
                    dl[0] = __halves2half2(l0, l1);
                    dl[1] = __halves2half2(l2, l3);
                }
            }
        }
        #pragma unroll
        for (int i = 0; i < W_F4; i++) {
            int idx = i * 256 + tid, r = idx >> 2, q = idx & 3;
            *(uint4*)(Bhi + buf * BSZ + r * LD + q * 8) = ph[i];
            if constexpr (NPASS == 3) *(uint4*)(Blo + buf * BSZ + r * LD + q * 8) = pl[i];
        }
    };

    loadS(0); storeS(0);
    __syncthreads();

    int buf = 0;
    for (int kt = 0; kt < KT; kt++) {
        if (kt + 1 < KT) loadS(kt + 1);
        const uint32_t aOH = sAh + buf * ASZ * 2;
        const uint32_t aOL = sAl + buf * ASZ * 2;
        const uint32_t bOH = sBh + buf * BSZ * 2;
        const uint32_t bOL = sBl + buf * BSZ * 2;

        #pragma unroll
        for (int k16 = 0; k16 < 32; k16 += 16) {
            uint32_t aH[MT][4], aL[MT][4];
            #pragma unroll
            for (int mt = 0; mt < MT; mt++) {
                int mrow = wm * WM + mt * 16 + lr;
                ldsm4(aH[mt][0], aH[mt][1], aH[mt][2], aH[mt][3],
                      aOH + (mrow * LD + k16 + lc2) * 2);
                if constexpr (NPASS >= 2)
                    ldsm4(aL[mt][0], aL[mt][1], aL[mt][2], aL[mt][3],
                          aOL + (mrow * LD + k16 + lc2) * 2);
            }
            #pragma unroll
            for (int ch = 0; ch < NCHUNK; ch++) {
                #pragma unroll
                for (int g2 = 0; g2 < NG; g2++) {
                    int nb = ch * BN + wn * WN + g2 * 16 + lr;
                    uint32_t b0, b1, b2, b3;
                    ldsm4(b0, b1, b2, b3, bOH + (nb * LD + k16 + lc2) * 2);
                    #pragma unroll
                    for (int mt = 0; mt < MT; mt++) {
                        mma16816(acc[ch][mt][2 * g2],     aH[mt], b0, b2);
                        mma16816(acc[ch][mt][2 * g2 + 1], aH[mt], b1, b3);
                    }
                    if constexpr (NPASS >= 2) {
                        #pragma unroll
                        for (int mt = 0; mt < MT; mt++) {
                            mma16816(acc[ch][mt][2 * g2],     aL[mt], b0, b2);
                            mma16816(acc[ch][mt][2 * g2 + 1], aL[mt], b1, b3);
                        }
                    }
                    if constexpr (NPASS == 3) {
                        uint32_t l0, l1, l2, l3;
                        ldsm4(l0, l1, l2, l3, bOL + (nb * LD + k16 + lc2) * 2);
                        #pragma unroll
                        for (int mt = 0; mt < MT; mt++) {
                            mma16816(acc[ch][mt][2 * g2],     aH[mt], l0, l2);
                            mma16816(acc[ch][mt][2 * g2 + 1], aH[mt], l1, l3);
                        }
                    }
                }
            }
        }
        if (kt + 1 < KT) storeS(buf ^ 1);
        __syncthreads();
        buf ^= 1;
    }

    // ---------------- epilogues ----------------
    if constexpr (MODE == 0) {
        float* Cf = (float*)Cout;
        #pragma unroll
        for (int mt = 0; mt < MT; mt++) {
            #pragma unroll
            for (int nt = 0; nt < NT; nt++) {
                int m = m0 + wm * WM + mt * 16 + g;
                int n = n0 + wn * WN + nt * 8 + 2 * c;
                if (n < NL) {
                    float b0 = bias ? bias[n] : 0.f;
                    float b1 = bias ? bias[n + 1] : 0.f;
                    *(float2*)(Cf + (size_t)m * NL + n) =
                        make_float2(acc[0][mt][nt][0] + b0, acc[0][mt][nt][1] + b1);
                    *(float2*)(Cf + (size_t)(m + 8) * NL + n) =
                        make_float2(acc[0][mt][nt][2] + b0, acc[0][mt][nt][3] + b1);
                }
            }
        }
    } else if constexpr (MODE == 1) {
        __half2* Ch = (__half2*)Cout;
        #pragma unroll
        for (int mt = 0; mt < MT; mt++) {
            #pragma unroll
            for (int nt = 0; nt < NT; nt++) {
                int m = m0 + wm * WM + mt * 16 + g;
                int n = n0 + wn * WN + nt * 8 + 2 * c;
                Ch[((size_t)m * 512 + n) >> 1] =
                    __floats2half2_rn(acc[0][mt][nt][0], acc[0][mt][nt][1]);
                Ch[((size_t)(m + 8) * 512 + n) >> 1] =
                    __floats2half2_rn(acc[0][mt][nt][2], acc[0][mt][nt][3]);
            }
        }
    } else {  // MODE 2: GRU fused epilogue
        #pragma unroll
        for (int mt = 0; mt < MT; mt++) {
            #pragma unroll
            for (int rowh = 0; rowh < 2; rowh++) {
                int b = m0 + wm * WM + mt * 16 + g + rowh * 8;
                int tg = (s == 0) ? 0 : g_text[b * S_DIM + s - 1];
                #pragma unroll
                for (int nt = 0; nt < NT; nt++) {
                    int n = n0 + wn * WN + nt * 8 + 2 * c;
                    int q = rowh * 2;
                    float arx = acc[0][mt][nt][q], ary = acc[0][mt][nt][q + 1];
                    float azx = acc[1][mt][nt][q], azy = acc[1][mt][nt][q + 1];
                    float anx = acc[2][mt][nt][q], any_ = acc[2][mt][nt][q + 1];
                    float2 hr = *(const float2*)&g_hpgh[b * 2048 + 512 + n];
                    float2 hz = *(const float2*)&g_hpgh[b * 2048 + 1024 + n];
                    float2 hn = *(const float2*)&g_hpgh[b * 2048 + 1536 + n];
                    float2 er = *(const float2*)&g_embtab[tg * 1536 + n];
                    float2 ez = *(const float2*)&g_embtab[tg * 1536 + 512 + n];
                    float2 en = *(const float2*)&g_embtab[tg * 1536 + 1024 + n];
                    float2 br = *(const float2*)&bias[n];
                    float2 bz = *(const float2*)&bias[512 + n];
                    float2 bn = *(const float2*)&bias[1024 + n];
                    float2 h  = *(const float2*)&g_hidden[b * 512 + n];
                    float rx = sigf(arx + br.x + er.x + hr.x);
                    float ry = sigf(ary + br.y + er.y + hr.y);
                    float zx = sigf(azx + bz.x + ez.x + hz.x);
                    float zy = sigf(azy + bz.y + ez.y + hz.y);
                    float nx = tanhf_fast(anx + bn.x + en.x + rx * hn.x);
                    float ny = tanhf_fast(any_ + bn.y + en.y + ry * hn.y);
                    float hx = (1.f - zx) * nx + zx * h.x;
                    float hy = (1.f - zy) * ny + zy * h.y;
                    *(float2*)&g_hidden[b * 512 + n] = make_float2(hx, hy);
                    *(float2*)&g_hs[((size_t)b * S_DIM + s) * 512 + n] = make_float2(hx, hy);
                }
            }
        }
    }
}

// ---------------- fused attention ----------------------------------------------
__global__ void att_kernel(const float* __restrict__ Wscore) {
    __shared__ float hpS[H_DIM];
    __shared__ float wS[H_DIM];
    __shared__ float eS[T_DIM];

    const int b = blockIdx.x;
    const int tid = threadIdx.x;
    const int warp = tid >> 5, lane = tid & 31;

    for (int h = tid; h < H_DIM; h += 256) {
        hpS[h] = g_hpgh[b * 2048 + h];
        wS[h] = Wscore[h];
    }
    __syncthreads();

    for (int t = warp; t < T_DIM; t += 8) {
        const __half2* fp = g_fproj_h2 + ((size_t)t * B_DIM + b) * (H_DIM / 2);
        float p = 0.f;
        #pragma unroll 4
        for (int i = lane; i < H_DIM / 2; i += 32) {
            float2 f = __half22float2(fp[i]);
            p += tanh_mufu(f.x + hpS[2 * i]) * wS[2 * i];
            p += tanh_mufu(f.y + hpS[2 * i + 1]) * wS[2 * i + 1];
        }
        #pragma unroll
        for (int off = 16; off; off >>= 1) p += __shfl_xor_sync(0xFFFFFFFFu, p, off);
        if (lane == 0) eS[t] = p;
    }
    __syncthreads();

    if (tid < 32) {
        float e1 = eS[tid], e2 = eS[tid + 32];
        float m = fmaxf(e1, e2);
        #pragma unroll
        for (int off = 16; off; off >>= 1) m = fmaxf(m, __shfl_xor_sync(0xFFFFFFFFu, m, off));
        float x1 = __expf(e1 - m), x2 = __expf(e2 - m);
        float ssum = x1 + x2;
        #pragma unroll
        for (int off = 16; off; off >>= 1) ssum += __shfl_xor_sync(0xFFFFFFFFu, ssum, off);
        float inv = __fdividef(1.f, ssum);
        eS[tid] = x1 * inv;
        eS[tid + 32] = x2 * inv;
    }
    __syncthreads();

    {
        const __half2* fb = g_feat_h2 + (size_t)b * (C_DIM / 2) + tid;
        float cx = 0.f, cy = 0.f;
        #pragma unroll 8
        for (int t = 0; t < T_DIM; t++) {
            float2 f = __half22float2(fb[(size_t)t * B_DIM * (C_DIM / 2)]);
            float a = eS[t];
            cx = fmaf(a, f.x, cx);
            cy = fmaf(a, f.y, cy);
        }
        *(float2*)(g_x + b * 512 + 2 * tid) = make_float2(cx, cy);
    }
}

// ---------------- host ----------------------------------------------------------
struct Ptrs {
    float *hpgh, *x, *hidden, *hs, *bias_hpgh;
    __half2 *fproj_h2, *feat_h2;
    __half *whi, *wlo;
};

constexpr int SMEM_HPGH = (4 * 32 * 40 + 2 * 128 * 40) * 2;   // 30720
constexpr int SMEM_GRU  = (4 * 32 * 40 + 2 * 192 * 40) * 2;   // 40960
constexpr int SMEM_FP   = (2 * 128 * 40 + 2 * 128 * 40) * 2;  // 40960
constexpr int SMEM_FIN  = (4 * 64 * 40 + 4 * 128 * 40) * 2;   // 61440

extern "C" void kernel_launch(void* const* d_in, const int* in_sizes, int n_in,
                              void* d_out, int out_size)
{
    (void)in_sizes; (void)n_in; (void)out_size;
    const float* feature  = (const float*)d_in[0];
    const int*   text_raw = (const int*)  d_in[1];
    const float* W_h2h    = (const float*)d_in[2];
    const float* b_h2h    = (const float*)d_in[3];
    const float* W_c2h    = (const float*)d_in[4];
    const float* W_score  = (const float*)d_in[5];
    const float* W_ih     = (const float*)d_in[6];
    const float* W_hh     = (const float*)d_in[7];
    const float* b_ih     = (const float*)d_in[8];
    const float* b_hh     = (const float*)d_in[9];
    const float* char_emb = (const float*)d_in[10];
    const float* W_gen    = (const float*)d_in[11];
    const float* b_gen    = (const float*)d_in[12];
    float* out = (float*)d_out;

    static Ptrs P = [] {
        Ptrs p;
        cudaGetSymbolAddress((void**)&p.hpgh,      g_hpgh);
        cudaGetSymbolAddress((void**)&p.x,         g_x);
        cudaGetSymbolAddress((void**)&p.hidden,    g_hidden);
        cudaGetSymbolAddress((void**)&p.hs,        g_hs);
        cudaGetSymbolAddress((void**)&p.bias_hpgh, g_bias_hpgh);
        cudaGetSymbolAddress((void**)&p.fproj_h2,  g_fproj_h2);
        cudaGetSymbolAddress((void**)&p.feat_h2,   g_feat_h2);
        cudaGetSymbolAddress((void**)&p.whi,       g_Whi);
        cudaGetSymbolAddress((void**)&p.wlo,       g_Wlo);
        cudaFuncSetAttribute(gemm_f16<32, 128, 1, 2, 0, 0>,
                             cudaFuncAttributeMaxDynamicSharedMemorySize, SMEM_HPGH);
        cudaFuncSetAttribute(gemm_f16<32, 64, 3, 2, 2, 0>,
                             cudaFuncAttributeMaxDynamicSharedMemorySize, SMEM_GRU);
        cudaFuncSetAttribute(gemm_f16<128, 128, 1, 1, 1, 1>,
                             cudaFuncAttributeMaxDynamicSharedMemorySize, SMEM_FP);
        cudaFuncSetAttribute(gemm_f16<64, 128, 1, 3, 0, 0>,
                             cudaFuncAttributeMaxDynamicSharedMemorySize, SMEM_FIN);
        return p;
    }();

    // ---- prep: exactly 5 launches, then the loop (launch #6 = hpgh s=0)
    textnorm_kernel<<<1, 256>>>(text_raw);                                   // 1
    {
        int n2 = T_DIM * B_DIM * C_DIM / 2;
        tohalf_k<<<(n2 + 255) / 256, 256>>>(feature, P.feat_h2, n2);         // 2
    }
    presplit_all<<<(WROWS * 512 + 255) / 256, 256>>>(W_h2h, W_hh, W_ih,
                                                     W_gen, W_c2h,
                                                     b_h2h, b_hh);           // 3
    embtab_k<<<192, 256>>>(char_emb, W_ih);                                  // 4

    // fproj = feat16 @ W_c2h^T -> fp16  (M=32768, N=512) single-pass
    gemm_f16<128, 128, 1, 1, 1, 1><<<dim3(4, 256), 256, SMEM_FP>>>(
        P.feat_h2, P.whi + OFF_C2H, P.wlo + OFF_C2H, nullptr,
        P.fproj_h2, 512, 0);                                                 // 5

    for (int s = 0; s < S_DIM; s++) {
        // [hp | hr hz hn] = hidden @ [W_h2h; W_hh]^T + bias  (512 x 2048)
        gemm_f16<32, 128, 1, 2, 0, 0><<<dim3(16, 16), 256, SMEM_HPGH>>>(
            P.hidden, P.whi, P.wlo, P.bias_hpgh, P.hpgh, 2048, s);

        att_kernel<<<B_DIM, 256>>>(W_score);

        // gi (3 gate chunks) + GRU epilogue  (512 x 3x512 eff)
        gemm_f16<32, 64, 3, 2, 2, 0><<<dim3(8, 16), 256, SMEM_GRU>>>(
            P.x, P.whi + OFF_IH, P.wlo + OFF_IH, b_ih, nullptr, 512, s);
    }

    // probs = hs @ W_gen^T + b_gen  (16384 x 96), W padded to 128 rows
    gemm_f16<64, 128, 1, 3, 0, 0><<<dim3(1, 256), 256, SMEM_FIN>>>(
        P.hs, P.whi + OFF_GEN, P.wlo + OFF_GEN, b_gen, out, 96, 0);
}

// round 7
// speedup vs baseline: 4.1894x; 1.0684x over previous
#include <cuda_runtime.h>
#include <cuda_fp16.h>
#include <cstdint>
#include <cstddef>

#define T_DIM 64
#define B_DIM 512
#define C_DIM 512
#define H_DIM 512
#define E_DIM 128
#define NC_DIM 96
#define S_DIM 32

// Weight row layout inside the packed fp16 hi/lo arrays (all K=512):
//  rows [0,2048)    : [W_h2h ; W_hh]   (hpgh GEMM)
//  rows [2048,3584) : W_ih[:, 0:512]   (gi GEMM)
//  rows [3584,3712) : W_gen padded 96->128
//  rows [3712,4224) : W_c2h            (fproj GEMM)
#define WROWS 4224
#define OFF_IH  (2048 * 512)
#define OFF_GEN (3584 * 512)
#define OFF_C2H (3712 * 512)

// ---------------- scratch (device globals) ----------------------------------
__device__ __half2 g_fproj_h2[(size_t)T_DIM * B_DIM * (H_DIM / 2)];
__device__ __half2 g_feat_h2[(size_t)T_DIM * B_DIM * (C_DIM / 2)];
__device__ __half  g_Whi[(size_t)WROWS * 512];
__device__ __half  g_Wlo[(size_t)WROWS * 512];
__device__ float   g_embtab[96 * 1536];
__device__ float   g_hpgh[B_DIM * 2048];     // [B][ hp(512) | hr hz hn (3*512) ]
__device__ __half  g_x_h[B_DIM * 512];       // fp16 context (GEMM A input)
__device__ __half  g_hidden_h[B_DIM * 512];  // fp16 hidden (GEMM A input)
__device__ float   g_hs[(size_t)S_DIM * B_DIM * 512];   // fp32, rows (b*S+s)
__device__ int     g_text[B_DIM * S_DIM];
__device__ float   g_bias_hpgh[2048];

// ---------------- fast math helpers ------------------------------------------
__device__ __forceinline__ float sigf(float x) {
    return __fdividef(1.f, 1.f + __expf(-x));
}
__device__ __forceinline__ float tanhf_fast(float x) {
    x = fminf(fmaxf(x, -15.f), 15.f);
    float e = __expf(-2.f * x);
    return __fdividef(1.f - e, 1.f + e);
}
__device__ __forceinline__ float tanh_mufu(float x) {
    float y;
    asm("tanh.approx.f32 %0, %1;" : "=f"(y) : "f"(x));
    return y;
}

// ---------------- mma / ldmatrix helpers --------------------------------------
__device__ __forceinline__ void ldsm4(uint32_t& r0, uint32_t& r1, uint32_t& r2,
                                      uint32_t& r3, uint32_t a) {
    asm volatile("ldmatrix.sync.aligned.m8n8.x4.shared.b16 {%0,%1,%2,%3}, [%4];"
                 : "=r"(r0), "=r"(r1), "=r"(r2), "=r"(r3) : "r"(a));
}
__device__ __forceinline__ void mma16816(float* d, const uint32_t* a, uint32_t b0, uint32_t b1) {
    asm volatile("mma.sync.aligned.m16n8k16.row.col.f32.f16.f16.f32 "
                 "{%0,%1,%2,%3},{%4,%5,%6,%7},{%8,%9},{%0,%1,%2,%3};"
                 : "+f"(d[0]), "+f"(d[1]), "+f"(d[2]), "+f"(d[3])
                 : "r"(a[0]), "r"(a[1]), "r"(a[2]), "r"(a[3]), "r"(b0), "r"(b1));
}

// ---------------- text dtype normalization ------------------------------------
__global__ void textnorm_kernel(const int* __restrict__ raw) {
    __shared__ int is32;
    int tid = threadIdx.x;
    if (tid == 0) is32 = 0;
    __syncthreads();
    int local = 0;
    for (int i = tid; i < 8192; i += blockDim.x) local |= raw[2 * i + 1];
    if (local) atomicOr(&is32, 1);
    __syncthreads();
    if (is32) {
        for (int i = tid; i < B_DIM * S_DIM; i += blockDim.x) g_text[i] = raw[i];
    } else {
        for (int i = tid; i < B_DIM * S_DIM; i += blockDim.x) g_text[i] = raw[2 * i];
    }
}

// ---------------- one-time transforms ------------------------------------------
// fp16 copy of feature + zero fp16 hidden
__global__ void tohalf_k(const float* __restrict__ src, __half2* __restrict__ dst, int n2) {
    int i = blockIdx.x * blockDim.x + threadIdx.x;
    if (i < n2) {
        float2 v = ((const float2*)src)[i];
        dst[i] = __floats2half2_rn(v.x, v.y);
    }
    if (i < B_DIM * 512 / 4)
        ((uint2*)g_hidden_h)[i] = make_uint2(0u, 0u);
}

__global__ void presplit_all(const float* __restrict__ W_h2h, const float* __restrict__ W_hh,
                             const float* __restrict__ W_ih, const float* __restrict__ W_gen,
                             const float* __restrict__ W_c2h,
                             const float* __restrict__ b_h2h, const float* __restrict__ b_hh) {
    int idx = blockIdx.x * 256 + threadIdx.x;
    if (idx >= WROWS * 512) return;
    if (idx < 2048)
        g_bias_hpgh[idx] = (idx < 512) ? b_h2h[idx] : b_hh[idx - 512];
    int row = idx >> 9, k = idx & 511;
    float v;
    if (row < 512)        v = W_h2h[row * 512 + k];
    else if (row < 2048)  v = W_hh[(row - 512) * 512 + k];
    else if (row < 3584)  v = W_ih[(size_t)(row - 2048) * 640 + k];
    else if (row < 3712) { int r = row - 3584; v = (r < 96) ? W_gen[r * 512 + k] : 0.f; }
    else                  v = W_c2h[(row - 3712) * 512 + k];
    __half h = __float2half_rn(v);
    g_Whi[idx] = h;
    g_Wlo[idx] = __float2half_rn(v - __half2float(h));
}

// embtab[t][n] = sum_j char_emb[t][j] * W_ih[n][512+j]  (fp32 exact)
__global__ void embtab_k(const float* __restrict__ char_emb, const float* __restrict__ W_ih) {
    __shared__ float e[96][128];
    int tid = threadIdx.x;
    for (int i = tid; i < 96 * 128; i += 256)
        e[i >> 7][i & 127] = char_emb[i];
    __syncthreads();
    int warp = tid >> 5, lane = tid & 31;
    int n = blockIdx.x * 8 + warp;
    float4 wv = *(const float4*)(W_ih + (size_t)n * 640 + 512 + lane * 4);
    for (int t = 0; t < 96; t++) {
        float4 ev = *(const float4*)(&e[t][lane * 4]);
        float p = wv.x * ev.x + wv.y * ev.y + wv.z * ev.z + wv.w * ev.w;
        #pragma unroll
        for (int off = 16; off; off >>= 1) p += __shfl_xor_sync(0xFFFFFFFFu, p, off);
        if (lane == 0) g_embtab[t * 1536 + n] = p;
    }
}

// ---------------- fp16 tensor-core GEMM ----------------------------------------
// C[M, N] = A[M,512] @ W[N,512]^T (+bias).
// NPASS: 1 = aH*bH; 2 = +aL*bH; 3 = +aH*bL (fp32 A only).
// MODE 0: fp32 out + bias (ldc=NL). MODE 1: fp16 out (ldc=512). MODE 2: gi+GRU fused.
// A16: A is fp16 (ld 512 halves), no split.
template<int BM, int BN, int NCHUNK, int NPASS, int MODE, int A16>
__global__ void __launch_bounds__(256, 1)
gemm_f16(const void* __restrict__ Ain,
         const __half* __restrict__ Whi, const __half* __restrict__ Wlo,
         const float* __restrict__ bias, void* __restrict__ Cout,
         int NL, int s)
{
    constexpr int LD = 40;          // fp16 row stride: 80B, conflict-free ldmatrix
    constexpr int BNR = BN * NCHUNK;
    constexpr int KT = 16;          // K = 512, BK = 32
    constexpr int WM = BM / 2, WN = BN / 4;
    constexpr int MT = WM / 16, NT = WN / 8, NG = NT / 2;
    static_assert(MT >= 1 && NG >= 1, "tile config");
    constexpr int ASZ = BM * LD;
    constexpr int BSZ = BNR * LD;
    constexpr int A_F4 = BM / 32;
    constexpr int A_LOADS = BM * 4;                   // uint4s per A stage (A16)
    constexpr int A_PER_T = (A_LOADS + 255) / 256;
    constexpr int W_F4 = BNR / 64;

    extern __shared__ __half sh[];
    __half* Ahi = sh;
    __half* Alo = (!A16 && NPASS >= 2) ? (Ahi + 2 * ASZ) : Ahi;
    __half* Bhi = Ahi + ((!A16 && NPASS >= 2) ? 4 : 2) * ASZ;
    __half* Blo = (NPASS == 3) ? (Bhi + 2 * BSZ) : Bhi;

    const int tid = threadIdx.x;
    const int warp = tid >> 5, lane = tid & 31;
    const int g = lane >> 2, c = lane & 3;
    const int wm = warp & 1, wn = warp >> 1;
    const int m0 = blockIdx.y * BM, n0 = blockIdx.x * BN;
    const int lr = lane & 15, lc2 = (lane >> 4) << 3;

    const uint32_t sAh = (uint32_t)__cvta_generic_to_shared(Ahi);
    const uint32_t sAl = (uint32_t)__cvta_generic_to_shared(Alo);
    const uint32_t sBh = (uint32_t)__cvta_generic_to_shared(Bhi);
    const uint32_t sBl = (uint32_t)__cvta_generic_to_shared(Blo);

    float acc[NCHUNK][MT][NT][4];
    #pragma unroll
    for (int ch = 0; ch < NCHUNK; ch++)
        #pragma unroll
        for (int i = 0; i < MT; i++)
            #pragma unroll
            for (int j = 0; j < NT; j++)
                #pragma unroll
                for (int q = 0; q < 4; q++) acc[ch][i][j][q] = 0.f;

    float4 pa[A16 ? 1 : A_F4];
    uint4 pah[A16 ? A_PER_T : 1];
    uint4 ph[W_F4], pl[W_F4];

    auto loadS = [&](int kt) {
        if constexpr (A16) {
            const __half* Ah16 = (const __half*)Ain;
            #pragma unroll
            for (int i = 0; i < A_PER_T; i++) {
                int idx = i * 256 + tid;
                if (A_LOADS % 256 == 0 || idx < A_LOADS) {
                    int r = idx >> 2, q = idx & 3;
                    pah[i] = *(const uint4*)(Ah16 + (size_t)(m0 + r) * 512 + kt * 32 + q * 8);
                }
            }
        } else {
            const float* Af = (const float*)Ain;
            #pragma unroll
            for (int i = 0; i < A_F4; i++) {
                int idx = i * 256 + tid, r = idx >> 3, kq = (idx & 7) << 2;
                pa[i] = *(const float4*)(Af + (size_t)(m0 + r) * 512 + kt * 32 + kq);
            }
        }
        #pragma unroll
        for (int i = 0; i < W_F4; i++) {
            int idx = i * 256 + tid, r = idx >> 2, q = idx & 3;
            int ch = r / BN;
            int row = ch * 512 + n0 + (r - ch * BN);
            size_t off = (size_t)row * 512 + kt * 32 + q * 8;
            ph[i] = *(const uint4*)(Whi + off);
            if constexpr (NPASS == 3) pl[i] = *(const uint4*)(Wlo + off);
        }
    };
    auto storeS = [&](int buf) {
        if constexpr (A16) {
            #pragma unroll
            for (int i = 0; i < A_PER_T; i++) {
                int idx = i * 256 + tid;
                if (A_LOADS % 256 == 0 || idx < A_LOADS) {
                    int r = idx >> 2, q = idx & 3;
                    *(uint4*)(Ahi + buf * ASZ + r * LD + q * 8) = pah[i];
                }
            }
        } else {
            #pragma unroll
            for (int i = 0; i < A_F4; i++) {
                int idx = i * 256 + tid, r = idx >> 3, kq = (idx & 7) << 2;
                float4 v = pa[i];
                __half h0 = __float2half_rn(v.x), h1 = __float2half_rn(v.y);
                __half h2 = __float2half_rn(v.z), h3 = __float2half_rn(v.w);
                __half2* d = (__half2*)(Ahi + buf * ASZ + r * LD + kq);
                d[0] = __halves2half2(h0, h1);
                d[1] = __halves2half2(h2, h3);
                if constexpr (NPASS >= 2) {
                    __half l0 = __float2half_rn(v.x - __half2float(h0));
                    __half l1 = __float2half_rn(v.y - __half2float(h1));
                    __half l2 = __float2half_rn(v.z - __half2float(h2));
                    __half l3 = __float2half_rn(v.w - __half2float(h3));
                    __half2* dl = (__half2*)(Alo + buf * ASZ + r * LD + kq);
                    dl[0] = __halves2half2(l0, l1);
                    dl[1] = __halves2half2(l2, l3);
                }
            }
        }
        #pragma unroll
        for (int i = 0; i < W_F4; i++) {
            int idx = i * 256 + tid, r = idx >> 2, q = idx & 3;
            *(uint4*)(Bhi + buf * BSZ + r * LD + q * 8) = ph[i];
            if constexpr (NPASS == 3) *(uint4*)(Blo + buf * BSZ + r * LD + q * 8) = pl[i];
        }
    };

    loadS(0); storeS(0);
    __syncthreads();

    int buf = 0;
    for (int kt = 0; kt < KT; kt++) {
        if (kt + 1 < KT) loadS(kt + 1);
        const uint32_t aOH = sAh + buf * ASZ * 2;
        const uint32_t aOL = sAl + buf * ASZ * 2;
        const uint32_t bOH = sBh + buf * BSZ * 2;
        const uint32_t bOL = sBl + buf * BSZ * 2;

        #pragma unroll
        for (int k16 = 0; k16 < 32; k16 += 16) {
            uint32_t aH[MT][4], aL[MT][4];
            #pragma unroll
            for (int mt = 0; mt < MT; mt++) {
                int mrow = wm * WM + mt * 16 + lr;
                ldsm4(aH[mt][0], aH[mt][1], aH[mt][2], aH[mt][3],
                      aOH + (mrow * LD + k16 + lc2) * 2);
                if constexpr (!A16 && NPASS >= 2)
                    ldsm4(aL[mt][0], aL[mt][1], aL[mt][2], aL[mt][3],
                          aOL + (mrow * LD + k16 + lc2) * 2);
            }
            #pragma unroll
            for (int ch = 0; ch < NCHUNK; ch++) {
                #pragma unroll
                for (int g2 = 0; g2 < NG; g2++) {
                    int nb = ch * BN + wn * WN + g2 * 16 + lr;
                    uint32_t b0, b1, b2, b3;
                    ldsm4(b0, b1, b2, b3, bOH + (nb * LD + k16 + lc2) * 2);
                    #pragma unroll
                    for (int mt = 0; mt < MT; mt++) {
                        mma16816(acc[ch][mt][2 * g2],     aH[mt], b0, b2);
                        mma16816(acc[ch][mt][2 * g2 + 1], aH[mt], b1, b3);
                    }
                    if constexpr (!A16 && NPASS >= 2) {
                        #pragma unroll
                        for (int mt = 0; mt < MT; mt++) {
                            mma16816(acc[ch][mt][2 * g2],     aL[mt], b0, b2);
                            mma16816(acc[ch][mt][2 * g2 + 1], aL[mt], b1, b3);
                        }
                    }
                    if constexpr (NPASS == 3) {
                        uint32_t l0, l1, l2, l3;
                        ldsm4(l0, l1, l2, l3, bOL + (nb * LD + k16 + lc2) * 2);
                        #pragma unroll
                        for (int mt = 0; mt < MT; mt++) {
                            mma16816(acc[ch][mt][2 * g2],     aH[mt], l0, l2);
                            mma16816(acc[ch][mt][2 * g2 + 1], aH[mt], l1, l3);
                        }
                    }
                }
            }
        }
        if (kt + 1 < KT) storeS(buf ^ 1);
        __syncthreads();
        buf ^= 1;
    }

    // ---------------- epilogues ----------------
    if constexpr (MODE == 0) {
        float* Cf = (float*)Cout;
        #pragma unroll
        for (int mt = 0; mt < MT; mt++) {
            #pragma unroll
            for (int nt = 0; nt < NT; nt++) {
                int m = m0 + wm * WM + mt * 16 + g;
                int n = n0 + wn * WN + nt * 8 + 2 * c;
                if (n < NL) {
                    float b0 = bias ? bias[n] : 0.f;
                    float b1 = bias ? bias[n + 1] : 0.f;
                    *(float2*)(Cf + (size_t)m * NL + n) =
                        make_float2(acc[0][mt][nt][0] + b0, acc[0][mt][nt][1] + b1);
                    *(float2*)(Cf + (size_t)(m + 8) * NL + n) =
                        make_float2(acc[0][mt][nt][2] + b0, acc[0][mt][nt][3] + b1);
                }
            }
        }
    } else if constexpr (MODE == 1) {
        __half2* Ch = (__half2*)Cout;
        #pragma unroll
        for (int mt = 0; mt < MT; mt++) {
            #pragma unroll
            for (int nt = 0; nt < NT; nt++) {
                int m = m0 + wm * WM + mt * 16 + g;
                int n = n0 + wn * WN + nt * 8 + 2 * c;
                Ch[((size_t)m * 512 + n) >> 1] =
                    __floats2half2_rn(acc[0][mt][nt][0], acc[0][mt][nt][1]);
                Ch[((size_t)(m + 8) * 512 + n) >> 1] =
                    __floats2half2_rn(acc[0][mt][nt][2], acc[0][mt][nt][3]);
            }
        }
    } else {  // MODE 2: GRU fused epilogue
        #pragma unroll
        for (int mt = 0; mt < MT; mt++) {
            #pragma unroll
            for (int rowh = 0; rowh < 2; rowh++) {
                int b = m0 + wm * WM + mt * 16 + g + rowh * 8;
                int tg = (s == 0) ? 0 : g_text[b * S_DIM + s - 1];
                #pragma unroll
                for (int nt = 0; nt < NT; nt++) {
                    int n = n0 + wn * WN + nt * 8 + 2 * c;
                    int q = rowh * 2;
                    float arx = acc[0][mt][nt][q], ary = acc[0][mt][nt][q + 1];
                    float azx = acc[1][mt][nt][q], azy = acc[1][mt][nt][q + 1];
                    float anx = acc[2][mt][nt][q], any_ = acc[2][mt][nt][q + 1];
                    float2 hr = *(const float2*)&g_hpgh[b * 2048 + 512 + n];
                    float2 hz = *(const float2*)&g_hpgh[b * 2048 + 1024 + n];
                    float2 hn = *(const float2*)&g_hpgh[b * 2048 + 1536 + n];
                    float2 er = *(const float2*)&g_embtab[tg * 1536 + n];
                    float2 ez = *(const float2*)&g_embtab[tg * 1536 + 512 + n];
                    float2 en = *(const float2*)&g_embtab[tg * 1536 + 1024 + n];
                    float2 br = *(const float2*)&bias[n];
                    float2 bz = *(const float2*)&bias[512 + n];
                    float2 bn = *(const float2*)&bias[1024 + n];
                    float2 h = (s > 0)
                        ? *(const float2*)&g_hs[((size_t)b * S_DIM + s - 1) * 512 + n]
                        : make_float2(0.f, 0.f);
                    float rx = sigf(arx + br.x + er.x + hr.x);
                    float ry = sigf(ary + br.y + er.y + hr.y);
                    float zx = sigf(azx + bz.x + ez.x + hz.x);
                    float zy = sigf(azy + bz.y + ez.y + hz.y);
                    float nx = tanhf_fast(anx + bn.x + en.x + rx * hn.x);
                    float ny = tanhf_fast(any_ + bn.y + en.y + ry * hn.y);
                    float hx = (1.f - zx) * nx + zx * h.x;
                    float hy = (1.f - zy) * ny + zy * h.y;
                    *(float2*)&g_hs[((size_t)b * S_DIM + s) * 512 + n] = make_float2(hx, hy);
                    *(__half2*)&g_hidden_h[b * 512 + n] = __floats2half2_rn(hx, hy);
                }
            }
        }
    }
}

// ---------------- fused attention ----------------------------------------------
__global__ void att_kernel(const float* __restrict__ Wscore) {
    __shared__ float hpS[H_DIM];
    __shared__ float wS[H_DIM];
    __shared__ float eS[T_DIM];

    const int b = blockIdx.x;
    const int tid = threadIdx.x;
    const int warp = tid >> 5, lane = tid & 31;

    for (int h = tid; h < H_DIM; h += 256) {
        hpS[h] = g_hpgh[b * 2048 + h];
        wS[h] = Wscore[h];
    }
    __syncthreads();

    // e[t] = sum_h tanh(fproj + hp) * w ; uint4 loads (8 halves/lane)
    for (int t = warp; t < T_DIM; t += 8) {
        const __half* fp = (const __half*)(g_fproj_h2 + ((size_t)t * B_DIM + b) * (H_DIM / 2));
        float p = 0.f;
        #pragma unroll
        for (int i0 = lane * 8; i0 < H_DIM; i0 += 256) {
            uint4 u = *(const uint4*)(fp + i0);
            const __half2* hh = (const __half2*)&u;
            #pragma unroll
            for (int j = 0; j < 4; j++) {
                float2 f = __half22float2(hh[j]);
                p += tanh_mufu(f.x + hpS[i0 + 2 * j]) * wS[i0 + 2 * j];
                p += tanh_mufu(f.y + hpS[i0 + 2 * j + 1]) * wS[i0 + 2 * j + 1];
            }
        }
        #pragma unroll
        for (int off = 16; off; off >>= 1) p += __shfl_xor_sync(0xFFFFFFFFu, p, off);
        if (lane == 0) eS[t] = p;
    }
    __syncthreads();

    if (tid < 32) {
        float e1 = eS[tid], e2 = eS[tid + 32];
        float m = fmaxf(e1, e2);
        #pragma unroll
        for (int off = 16; off; off >>= 1) m = fmaxf(m, __shfl_xor_sync(0xFFFFFFFFu, m, off));
        float x1 = __expf(e1 - m), x2 = __expf(e2 - m);
        float ssum = x1 + x2;
        #pragma unroll
        for (int off = 16; off; off >>= 1) ssum += __shfl_xor_sync(0xFFFFFFFFu, ssum, off);
        float inv = __fdividef(1.f, ssum);
        eS[tid] = x1 * inv;
        eS[tid + 32] = x2 * inv;
    }
    __syncthreads();

    // context -> fp16 x
    {
        const __half2* fb = g_feat_h2 + (size_t)b * (C_DIM / 2) + tid;
        float cx = 0.f, cy = 0.f;
        #pragma unroll 8
        for (int t = 0; t < T_DIM; t++) {
            float2 f = __half22float2(fb[(size_t)t * B_DIM * (C_DIM / 2)]);
            float a = eS[t];
            cx = fmaf(a, f.x, cx);
            cy = fmaf(a, f.y, cy);
        }
        *(__half2*)&g_x_h[b * 512 + 2 * tid] = __floats2half2_rn(cx, cy);
    }
}

// ---------------- host ----------------------------------------------------------
struct Ptrs {
    float *hpgh, *hs, *bias_hpgh;
    __half *x_h, *hidden_h;
    __half2 *fproj_h2, *feat_h2;
    __half *whi, *wlo;
};

constexpr int SMEM_HPGH = (2 * 32 * 40 + 2 * 128 * 40) * 2;   // 25600
constexpr int SMEM_GRU  = (2 * 32 * 40 + 2 * 192 * 40) * 2;   // 35840
constexpr int SMEM_FP   = (2 * 128 * 40 + 2 * 128 * 40) * 2;  // 40960
constexpr int SMEM_FIN  = (4 * 64 * 40 + 4 * 128 * 40) * 2;   // 61440

extern "C" void kernel_launch(void* const* d_in, const int* in_sizes, int n_in,
                              void* d_out, int out_size)
{
    (void)in_sizes; (void)n_in; (void)out_size;
    const float* feature  = (const float*)d_in[0];
    const int*   text_raw = (const int*)  d_in[1];
    const float* W_h2h    = (const float*)d_in[2];
    const float* b_h2h    = (const float*)d_in[3];
    const float* W_c2h    = (const float*)d_in[4];
    const float* W_score  = (const float*)d_in[5];
    const float* W_ih     = (const float*)d_in[6];
    const float* W_hh     = (const float*)d_in[7];
    const float* b_ih     = (const float*)d_in[8];
    const float* b_hh     = (const float*)d_in[9];
    const float* char_emb = (const float*)d_in[10];
    const float* W_gen    = (const float*)d_in[11];
    const float* b_gen    = (const float*)d_in[12];
    float* out = (float*)d_out;

    static Ptrs P = [] {
        Ptrs p;
        cudaGetSymbolAddress((void**)&p.hpgh,      g_hpgh);
        cudaGetSymbolAddress((void**)&p.hs,        g_hs);
        cudaGetSymbolAddress((void**)&p.bias_hpgh, g_bias_hpgh);
        cudaGetSymbolAddress((void**)&p.x_h,       g_x_h);
        cudaGetSymbolAddress((void**)&p.hidden_h,  g_hidden_h);
        cudaGetSymbolAddress((void**)&p.fproj_h2,  g_fproj_h2);
        cudaGetSymbolAddress((void**)&p.feat_h2,   g_feat_h2);
        cudaGetSymbolAddress((void**)&p.whi,       g_Whi);
        cudaGetSymbolAddress((void**)&p.wlo,       g_Wlo);
        cudaFuncSetAttribute(gemm_f16<32, 128, 1, 1, 0, 1>,
                             cudaFuncAttributeMaxDynamicSharedMemorySize, SMEM_HPGH);
        cudaFuncSetAttribute(gemm_f16<32, 64, 3, 1, 2, 1>,
                             cudaFuncAttributeMaxDynamicSharedMemorySize, SMEM_GRU);
        cudaFuncSetAttribute(gemm_f16<128, 128, 1, 1, 1, 1>,
                             cudaFuncAttributeMaxDynamicSharedMemorySize, SMEM_FP);
        cudaFuncSetAttribute(gemm_f16<64, 128, 1, 3, 0, 0>,
                             cudaFuncAttributeMaxDynamicSharedMemorySize, SMEM_FIN);
        return p;
    }();

    // ---- prep
    textnorm_kernel<<<1, 256>>>(text_raw);
    {
        int n2 = T_DIM * B_DIM * C_DIM / 2;
        tohalf_k<<<(n2 + 255) / 256, 256>>>(feature, P.feat_h2, n2);
    }
    presplit_all<<<(WROWS * 512 + 255) / 256, 256>>>(W_h2h, W_hh, W_ih,
                                                     W_gen, W_c2h,
                                                     b_h2h, b_hh);
    embtab_k<<<192, 256>>>(char_emb, W_ih);

    // fproj = feat16 @ W_c2h^T -> fp16  (M=32768, N=512)
    gemm_f16<128, 128, 1, 1, 1, 1><<<dim3(4, 256), 256, SMEM_FP>>>(
        P.feat_h2, P.whi + OFF_C2H, P.wlo + OFF_C2H, nullptr,
        P.fproj_h2, 512, 0);

    for (int s = 0; s < S_DIM; s++) {
        // [hp | hr hz hn] = hidden16 @ [W_h2h; W_hh]^T + bias  (512 x 2048, 1-pass)
        gemm_f16<32, 128, 1, 1, 0, 1><<<dim3(16, 16), 256, SMEM_HPGH>>>(
            P.hidden_h, P.whi, P.wlo, P.bias_hpgh, P.hpgh, 2048, s);

        att_kernel<<<B_DIM, 256>>>(W_score);

        // gi (3 gate chunks) + GRU epilogue  (x16, 1-pass)
        gemm_f16<32, 64, 3, 1, 2, 1><<<dim3(8, 16), 256, SMEM_GRU>>>(
            P.x_h, P.whi + OFF_IH, P.wlo + OFF_IH, b_ih, nullptr, 512, s);
    }

    // probs = hs(fp32) @ W_gen^T + b_gen  (16384 x 96, 3-pass)
    gemm_f16<64, 128, 1, 3, 0, 0><<<dim3(1, 256), 256, SMEM_FIN>>>(
        P.hs, P.whi + OFF_GEN, P.wlo + OFF_GEN, b_gen, out, 96, 0);
}